// round 1
// baseline (speedup 1.0000x reference)
#include <cuda_runtime.h>

// ---------------------------------------------------------------------------
// SampleAndAggregate (GraphSAGE, 2-layer maxpool) — fp32 baseline
//
// Pipeline:
//   1. sample1/sample2: neighbor index expansion (both batches)
//   2. H_all = relu(features @ W_pool0 + b_pool0) for ALL 100000 nodes (shared)
//   3. per batch:
//        pool1 = segmax_25(H_all[s2])          [5120,512]
//        pool0 = segmax_10(H_all[s1])          [512,512]
//        y1 = relu(concat(feat[s1]@Ws0, pool1@Wn0))   [5120,256]
//        y0 = relu(concat(feat[b ]@Ws0, pool0@Wn0))   [512,256]
//        T  = relu(y1 @ W_pool1 + b_pool1)     [5120,512]
//        pool2 = segmax_10(T, consecutive)     [512,512]
//        out = l2norm(concat(y0@Ws1, pool2@Wn1))      [512,256]
// ---------------------------------------------------------------------------

#define BATCH 512
#define FEAT  256
#define HIDW  512
#define DOUT  128
#define DEG   128
#define NN    100000
#define NS_A  25      // NUM_SAMPLES[0]
#define NS_B  10      // NUM_SAMPLES[1]
#define N1    (BATCH*NS_B)     // 5120
#define N2    (N1*NS_A)        // 128000

// ------------------------- scratch (device globals) ------------------------
__device__ int   g_s1[2*N1];
__device__ int   g_s2[2*N2];
__device__ float g_H[(size_t)NN*HIDW];           // 204.8 MB
__device__ float g_pool1[2*(size_t)N1*HIDW];
__device__ float g_pool0[2*(size_t)BATCH*HIDW];
__device__ float g_y1[2*(size_t)N1*2*DOUT];
__device__ float g_y0[2*(size_t)BATCH*2*DOUT];
__device__ float g_T[2*(size_t)N1*HIDW];
__device__ float g_pool2[2*(size_t)BATCH*HIDW];

// ------------------------------- sampling ----------------------------------
__global__ void k_sample1(const int* __restrict__ b1, const int* __restrict__ b2,
                          const int* __restrict__ adj) {
    int i = blockIdx.x * blockDim.x + threadIdx.x;
    if (i >= 2 * N1) return;
    int t = i / N1, r = i % N1;
    int n = r / NS_B, j = r % NS_B;
    int node = (t ? b2 : b1)[n];
    g_s1[t * N1 + r] = adj[(size_t)node * DEG + j];
}

__global__ void k_sample2(const int* __restrict__ adj) {
    int i = blockIdx.x * blockDim.x + threadIdx.x;
    if (i >= 2 * N2) return;
    int t = i / N2, r = i % N2;
    int n = r / NS_A, j = r % NS_A;
    int parent = g_s1[t * N1 + n];
    g_s2[t * N2 + r] = adj[(size_t)parent * DEG + j];
}

// ------------------------------- tiled GEMM ---------------------------------
// C[row, col] = act( (gather ? A[gidx[row]] : A[row]) @ W + bias ),
// A row-major [*, K], W row-major [K, N], C row stride ldc.
template<int BM, int BN, int BK, int TM, int TN, bool RELU>
__global__ __launch_bounds__(256)
void k_gemm(const float* __restrict__ A, const int* __restrict__ gidx,
            int M, int K,
            const float* __restrict__ W, int N,
            const float* __restrict__ bias,
            float* __restrict__ C, int ldc)
{
    constexpr int TX = BN / TN;            // threads along n
    constexpr int TY = BM / TM;            // threads along m
    static_assert(TX * TY == 256, "thread count");
    constexpr int A4 = BM * BK / (4 * 256);
    constexpr int B4 = BK * BN / (4 * 256);

    __shared__ __align__(16) float As[BK][BM + 4];
    __shared__ __align__(16) float Bs[BK][BN];

    const int tid = threadIdx.x;
    const int tx = tid % TX, ty = tid / TX;
    const int m0 = blockIdx.x * BM;
    const int n0 = blockIdx.y * BN;

    float acc[TM][TN];
#pragma unroll
    for (int i = 0; i < TM; i++)
#pragma unroll
        for (int j = 0; j < TN; j++) acc[i][j] = 0.f;

    for (int kk = 0; kk < K; kk += BK) {
#pragma unroll
        for (int i = 0; i < A4; i++) {
            int f = tid + i * 256;
            int m = f / (BK / 4);
            int kq = f % (BK / 4);
            float4 v = make_float4(0.f, 0.f, 0.f, 0.f);
            int row = m0 + m;
            if (row < M) {
                int r = gidx ? gidx[row] : row;
                v = *(const float4*)(A + (size_t)r * K + kk + kq * 4);
            }
            As[kq * 4 + 0][m] = v.x;
            As[kq * 4 + 1][m] = v.y;
            As[kq * 4 + 2][m] = v.z;
            As[kq * 4 + 3][m] = v.w;
        }
#pragma unroll
        for (int i = 0; i < B4; i++) {
            int f = tid + i * 256;
            int kr = f / (BN / 4);
            int nq = f % (BN / 4);
            *(float4*)(&Bs[kr][nq * 4]) =
                *(const float4*)(W + (size_t)(kk + kr) * N + n0 + nq * 4);
        }
        __syncthreads();

#pragma unroll
        for (int k = 0; k < BK; k++) {
            float a[TM], b[TN];
#pragma unroll
            for (int i = 0; i < TM; i += 4)
                *(float4*)&a[i] = *(const float4*)&As[k][ty * TM + i];
#pragma unroll
            for (int j = 0; j < TN; j += 4)
                *(float4*)&b[j] = *(const float4*)&Bs[k][tx * TN + j];
#pragma unroll
            for (int i = 0; i < TM; i++)
#pragma unroll
                for (int j = 0; j < TN; j++)
                    acc[i][j] += a[i] * b[j];
        }
        __syncthreads();
    }

#pragma unroll
    for (int i = 0; i < TM; i++) {
        int row = m0 + ty * TM + i;
        if (row >= M) continue;
#pragma unroll
        for (int j = 0; j < TN; j += 4) {
            int col = n0 + tx * TN + j;
            float4 v;
            v.x = acc[i][j + 0];
            v.y = acc[i][j + 1];
            v.z = acc[i][j + 2];
            v.w = acc[i][j + 3];
            if (bias) {
                v.x += bias[col + 0];
                v.y += bias[col + 1];
                v.z += bias[col + 2];
                v.w += bias[col + 3];
            }
            if (RELU) {
                v.x = fmaxf(v.x, 0.f);
                v.y = fmaxf(v.y, 0.f);
                v.z = fmaxf(v.z, 0.f);
                v.w = fmaxf(v.w, 0.f);
            }
            *(float4*)(C + (size_t)row * ldc + col) = v;
        }
    }
}

// --------------------------- segmented gather-max ---------------------------
// dst[g, :512] = max_{j<NB} src[idx(g,j), :512]; idx==nullptr -> consecutive.
template<int NB>
__global__ void k_poolmax(const float* __restrict__ src, const int* __restrict__ idx,
                          float* __restrict__ dst)
{
    int g = blockIdx.x;
    __shared__ int sidx[NB];
    if (threadIdx.x < NB)
        sidx[threadIdx.x] = idx ? idx[g * NB + threadIdx.x] : g * NB + threadIdx.x;
    __syncthreads();
    int c = threadIdx.x * 4;     // 128 threads cover 512 cols
    float4 m = make_float4(-1e30f, -1e30f, -1e30f, -1e30f);
#pragma unroll
    for (int j = 0; j < NB; j++) {
        const float4 v = *(const float4*)(src + (size_t)sidx[j] * HIDW + c);
        m.x = fmaxf(m.x, v.x);
        m.y = fmaxf(m.y, v.y);
        m.z = fmaxf(m.z, v.z);
        m.w = fmaxf(m.w, v.w);
    }
    *(float4*)(dst + (size_t)g * HIDW + c) = m;
}

// -------------------- layer-1 combine + L2 normalize ------------------------
__global__ void k_final(const float* __restrict__ y0, const float* __restrict__ p2,
                        const float* __restrict__ Ws1, const float* __restrict__ Wn1,
                        float* __restrict__ out)
{
    int n = blockIdx.x;
    __shared__ float ss[256];
    __shared__ float sp[512];
    __shared__ float red[256];
    int tid = threadIdx.x;       // 256 threads
    ss[tid] = y0[(size_t)n * 256 + tid];
    sp[tid] = p2[(size_t)n * 512 + tid];
    sp[256 + tid] = p2[(size_t)n * 512 + 256 + tid];
    __syncthreads();

    float acc = 0.f;
    if (tid < 128) {
#pragma unroll 8
        for (int k = 0; k < 256; k++) acc += ss[k] * Ws1[k * 128 + tid];
    } else {
        int c = tid - 128;
#pragma unroll 8
        for (int k = 0; k < 512; k++) acc += sp[k] * Wn1[k * 128 + c];
    }
    red[tid] = acc * acc;
    __syncthreads();
    for (int s = 128; s > 0; s >>= 1) {
        if (tid < s) red[tid] += red[tid + s];
        __syncthreads();
    }
    float inv = 1.f / fmaxf(sqrtf(red[0]), 1e-12f);
    out[(size_t)n * 256 + tid] = acc * inv;
}

// ------------------------------- launcher -----------------------------------
extern "C" void kernel_launch(void* const* d_in, const int* in_sizes, int n_in,
                              void* d_out, int out_size)
{
    (void)in_sizes; (void)n_in; (void)out_size;
    const int*   b1   = (const int*)d_in[0];
    const int*   b2   = (const int*)d_in[1];
    const float* feat = (const float*)d_in[2];
    const int*   adj  = (const int*)d_in[3];
    const float* Wp0  = (const float*)d_in[4];
    const float* bp0  = (const float*)d_in[5];
    const float* Wn0  = (const float*)d_in[6];
    const float* Ws0  = (const float*)d_in[7];
    const float* Wp1  = (const float*)d_in[8];
    const float* bp1  = (const float*)d_in[9];
    const float* Wn1  = (const float*)d_in[10];
    const float* Ws1  = (const float*)d_in[11];
    float* out = (float*)d_out;

    int *s1, *s2;
    float *H, *pool1, *pool0, *y1, *y0, *T, *pool2;
    cudaGetSymbolAddress((void**)&s1,    g_s1);
    cudaGetSymbolAddress((void**)&s2,    g_s2);
    cudaGetSymbolAddress((void**)&H,     g_H);
    cudaGetSymbolAddress((void**)&pool1, g_pool1);
    cudaGetSymbolAddress((void**)&pool0, g_pool0);
    cudaGetSymbolAddress((void**)&y1,    g_y1);
    cudaGetSymbolAddress((void**)&y0,    g_y0);
    cudaGetSymbolAddress((void**)&T,     g_T);
    cudaGetSymbolAddress((void**)&pool2, g_pool2);

    // 1) sampling
    k_sample1<<<(2 * N1 + 255) / 256, 256>>>(b1, b2, adj);
    k_sample2<<<(2 * N2 + 255) / 256, 256>>>(adj);

    // 2) H_all = relu(features @ W_pool0 + b_pool0)   [100000, 512]
    k_gemm<128, 128, 16, 8, 8, true>
        <<<dim3((NN + 127) / 128, HIDW / 128), 256>>>(
            feat, nullptr, NN, FEAT, Wp0, HIDW, bp0, H, HIDW);

    for (int t = 0; t < 2; t++) {
        const int* bt = t ? b2 : b1;
        float* y1t = y1 + (size_t)t * N1 * 256;
        float* y0t = y0 + (size_t)t * BATCH * 256;
        float* p1t = pool1 + (size_t)t * N1 * HIDW;
        float* p0t = pool0 + (size_t)t * BATCH * HIDW;
        float* Tt  = T + (size_t)t * N1 * HIDW;
        float* p2t = pool2 + (size_t)t * BATCH * HIDW;

        // 3) segmented gather-max pools over H_all
        k_poolmax<NS_A><<<N1, 128>>>(H, s2 + (size_t)t * N2, p1t);
        k_poolmax<NS_B><<<BATCH, 128>>>(H, s1 + (size_t)t * N1, p0t);

        // 4) layer-0 combine (relu distributes over concat)
        k_gemm<64, 128, 16, 4, 8, true><<<dim3(N1 / 64, 1), 256>>>(
            feat, s1 + (size_t)t * N1, N1, FEAT, Ws0, DOUT, nullptr, y1t, 256);
        k_gemm<64, 128, 16, 4, 8, true><<<dim3(N1 / 64, 1), 256>>>(
            p1t, nullptr, N1, HIDW, Wn0, DOUT, nullptr, y1t + 128, 256);
        k_gemm<64, 128, 16, 4, 8, true><<<dim3(BATCH / 64, 1), 256>>>(
            feat, bt, BATCH, FEAT, Ws0, DOUT, nullptr, y0t, 256);
        k_gemm<64, 128, 16, 4, 8, true><<<dim3(BATCH / 64, 1), 256>>>(
            p0t, nullptr, BATCH, HIDW, Wn0, DOUT, nullptr, y0t + 128, 256);

        // 5) layer-1 pool MLP + consecutive segmax
        k_gemm<64, 128, 16, 4, 8, true><<<dim3(N1 / 64, HIDW / 128), 256>>>(
            y1t, nullptr, N1, 256, Wp1, HIDW, bp1, Tt, HIDW);
        k_poolmax<NS_B><<<BATCH, 128>>>(Tt, nullptr, p2t);

        // 6) final combine + L2 normalize
        k_final<<<BATCH, 256>>>(y0t, p2t, Ws1, Wn1, out + (size_t)t * BATCH * 256);
    }
}

// round 2
// speedup vs baseline: 1.7290x; 1.7290x over previous
#include <cuda_runtime.h>
#include <cstdint>

// ---------------------------------------------------------------------------
// SampleAndAggregate (GraphSAGE, 2-layer maxpool)
// Round 2: TF32 mma.sync tensor-core GEMM for the large GEMMs.
// ---------------------------------------------------------------------------

#define BATCH 512
#define FEAT  256
#define HIDW  512
#define DOUT  128
#define DEG   128
#define NN    100000
#define NS_A  25
#define NS_B  10
#define N1    (BATCH*NS_B)     // 5120
#define N2    (N1*NS_A)        // 128000

// ------------------------- scratch (device globals) ------------------------
__device__ int   g_s1[2*N1];
__device__ int   g_s2[2*N2];
__device__ float g_H[(size_t)NN*HIDW];
__device__ float g_pool1[2*(size_t)N1*HIDW];
__device__ float g_pool0[2*(size_t)BATCH*HIDW];
__device__ float g_y1[2*(size_t)N1*2*DOUT];
__device__ float g_y0[2*(size_t)BATCH*2*DOUT];
__device__ float g_T[2*(size_t)N1*HIDW];
__device__ float g_pool2[2*(size_t)BATCH*HIDW];

// ------------------------------- sampling ----------------------------------
__global__ void k_sample1(const int* __restrict__ b1, const int* __restrict__ b2,
                          const int* __restrict__ adj) {
    int i = blockIdx.x * blockDim.x + threadIdx.x;
    if (i >= 2 * N1) return;
    int t = i / N1, r = i % N1;
    int n = r / NS_B, j = r % NS_B;
    int node = (t ? b2 : b1)[n];
    g_s1[t * N1 + r] = adj[(size_t)node * DEG + j];
}

__global__ void k_sample2(const int* __restrict__ adj) {
    int i = blockIdx.x * blockDim.x + threadIdx.x;
    if (i >= 2 * N2) return;
    int t = i / N2, r = i % N2;
    int n = r / NS_A, j = r % NS_A;
    int parent = g_s1[t * N1 + n];
    g_s2[t * N2 + r] = adj[(size_t)parent * DEG + j];
}

// --------------------------- TF32 tensor-core GEMM --------------------------
// C[row,:] = act((gather ? A[gidx[row]] : A[row]) @ W + bias)
// BM=128, BN=128, BK=16; 256 threads = 8 warps (2m x 4n), warp tile 64x32.

__device__ __forceinline__ uint32_t f2tf(float f) {
    uint32_t r;
    asm("cvt.rna.tf32.f32 %0, %1;" : "=r"(r) : "f"(f));
    return r;
}

__device__ __forceinline__ void mma_tf32(float c[4], uint32_t a0, uint32_t a1,
                                         uint32_t a2, uint32_t a3,
                                         uint32_t b0, uint32_t b1) {
    asm volatile(
        "mma.sync.aligned.m16n8k8.row.col.f32.tf32.tf32.f32 "
        "{%0,%1,%2,%3}, {%4,%5,%6,%7}, {%8,%9}, {%0,%1,%2,%3};"
        : "+f"(c[0]), "+f"(c[1]), "+f"(c[2]), "+f"(c[3])
        : "r"(a0), "r"(a1), "r"(a2), "r"(a3), "r"(b0), "r"(b1));
}

template<bool RELU>
__global__ __launch_bounds__(256)
void k_gemm_tc(const float* __restrict__ A, const int* __restrict__ gidx,
               int M, int K,
               const float* __restrict__ W, int N,
               const float* __restrict__ bias,
               float* __restrict__ C, int ldc)
{
    constexpr int BM = 128, BK = 16;
    __shared__ uint32_t As[2][BK][BM + 4];    // [k][m]
    __shared__ uint32_t Bs[2][BK][128 + 8];   // [k][n]

    const int tid  = threadIdx.x;
    const int lane = tid & 31;
    const int warp = tid >> 5;
    const int wm = warp >> 2;              // 0..1
    const int wn = warp & 3;               // 0..3
    const int m0g = blockIdx.x * BM;
    const int n0g = blockIdx.y * 128;
    const int mA  = tid >> 2;              // 0..127 (with i*? no: per-half)
    (void)mA;

    float acc[4][4][4];
#pragma unroll
    for (int i = 0; i < 4; i++)
#pragma unroll
        for (int j = 0; j < 4; j++)
#pragma unroll
            for (int r = 0; r < 4; r++) acc[i][j][r] = 0.f;

    float4 av[2], bv[2];
    // per-thread load coordinates (f = tid + i*256, i=0..1)
    //   A: m = f/4, kq = f%4   -> As[kq*4 + c][m]
    //   B: kr = f/32, nq = f%32 -> Bs[kr][nq*4 + c]
    auto load_regs = [&](int kk) {
#pragma unroll
        for (int i = 0; i < 2; i++) {
            int f = tid + i * 256;
            int m = f >> 2, kq = f & 3;
            int row = m0g + m;
            float4 v = make_float4(0.f, 0.f, 0.f, 0.f);
            if (row < M) {
                int r = gidx ? gidx[row] : row;
                v = *(const float4*)(A + (size_t)r * K + kk + kq * 4);
            }
            av[i] = v;
            int kr = f >> 5, nq = f & 31;
            bv[i] = *(const float4*)(W + (size_t)(kk + kr) * N + n0g + nq * 4);
        }
    };
    auto store_smem = [&](int buf) {
#pragma unroll
        for (int i = 0; i < 2; i++) {
            int f = tid + i * 256;
            int m = f >> 2, kq = f & 3;
            As[buf][kq * 4 + 0][m] = f2tf(av[i].x);
            As[buf][kq * 4 + 1][m] = f2tf(av[i].y);
            As[buf][kq * 4 + 2][m] = f2tf(av[i].z);
            As[buf][kq * 4 + 3][m] = f2tf(av[i].w);
            int kr = f >> 5, nq = f & 31;
            Bs[buf][kr][nq * 4 + 0] = f2tf(bv[i].x);
            Bs[buf][kr][nq * 4 + 1] = f2tf(bv[i].y);
            Bs[buf][kr][nq * 4 + 2] = f2tf(bv[i].z);
            Bs[buf][kr][nq * 4 + 3] = f2tf(bv[i].w);
        }
    };

    const int m_base = wm * 64;
    const int n_base = wn * 32;
    const int rql = lane >> 2;   // 0..7
    const int cql = lane & 3;    // 0..3

    load_regs(0);
    store_smem(0);
    __syncthreads();

    int buf = 0;
    const int ktiles = K / BK;
    for (int kt = 0; kt < ktiles; kt++) {
        if (kt + 1 < ktiles) load_regs((kt + 1) * BK);

#pragma unroll
        for (int k0 = 0; k0 < BK; k0 += 8) {
            uint32_t af[4][4], bf[4][2];
#pragma unroll
            for (int mt = 0; mt < 4; mt++) {
                int r = m_base + mt * 16 + rql;
                af[mt][0] = As[buf][k0 + cql][r];
                af[mt][1] = As[buf][k0 + cql][r + 8];
                af[mt][2] = As[buf][k0 + 4 + cql][r];
                af[mt][3] = As[buf][k0 + 4 + cql][r + 8];
            }
#pragma unroll
            for (int nt = 0; nt < 4; nt++) {
                int c = n_base + nt * 8 + rql;
                bf[nt][0] = Bs[buf][k0 + cql][c];
                bf[nt][1] = Bs[buf][k0 + 4 + cql][c];
            }
#pragma unroll
            for (int mt = 0; mt < 4; mt++)
#pragma unroll
                for (int nt = 0; nt < 4; nt++)
                    mma_tf32(acc[mt][nt], af[mt][0], af[mt][1], af[mt][2],
                             af[mt][3], bf[nt][0], bf[nt][1]);
        }

        if (kt + 1 < ktiles) {
            store_smem(buf ^ 1);
            __syncthreads();
            buf ^= 1;
        }
    }

    // epilogue
#pragma unroll
    for (int mt = 0; mt < 4; mt++) {
#pragma unroll
        for (int half = 0; half < 2; half++) {
            int row = m0g + m_base + mt * 16 + rql + half * 8;
            if (row >= M) continue;
#pragma unroll
            for (int nt = 0; nt < 4; nt++) {
                int col = n0g + n_base + nt * 8 + cql * 2;
                float2 v;
                v.x = acc[mt][nt][half * 2 + 0];
                v.y = acc[mt][nt][half * 2 + 1];
                if (bias) { v.x += bias[col]; v.y += bias[col + 1]; }
                if (RELU) { v.x = fmaxf(v.x, 0.f); v.y = fmaxf(v.y, 0.f); }
                *(float2*)(C + (size_t)row * ldc + col) = v;
            }
        }
    }
}

// ----------------------------- SIMT fp32 GEMM -------------------------------
// kept for the small (M=512) exact-fp32 GEMMs
template<int BM, int BN, int BK, int TM, int TN, bool RELU>
__global__ __launch_bounds__(256)
void k_gemm(const float* __restrict__ A, const int* __restrict__ gidx,
            int M, int K,
            const float* __restrict__ W, int N,
            const float* __restrict__ bias,
            float* __restrict__ C, int ldc)
{
    constexpr int TX = BN / TN;
    constexpr int TY = BM / TM;
    static_assert(TX * TY == 256, "thread count");
    constexpr int A4 = BM * BK / (4 * 256);
    constexpr int B4 = BK * BN / (4 * 256);

    __shared__ __align__(16) float As[BK][BM + 4];
    __shared__ __align__(16) float Bs[BK][BN];

    const int tid = threadIdx.x;
    const int tx = tid % TX, ty = tid / TX;
    const int m0 = blockIdx.x * BM;
    const int n0 = blockIdx.y * BN;

    float acc[TM][TN];
#pragma unroll
    for (int i = 0; i < TM; i++)
#pragma unroll
        for (int j = 0; j < TN; j++) acc[i][j] = 0.f;

    for (int kk = 0; kk < K; kk += BK) {
#pragma unroll
        for (int i = 0; i < A4; i++) {
            int f = tid + i * 256;
            int m = f / (BK / 4);
            int kq = f % (BK / 4);
            float4 v = make_float4(0.f, 0.f, 0.f, 0.f);
            int row = m0 + m;
            if (row < M) {
                int r = gidx ? gidx[row] : row;
                v = *(const float4*)(A + (size_t)r * K + kk + kq * 4);
            }
            As[kq * 4 + 0][m] = v.x;
            As[kq * 4 + 1][m] = v.y;
            As[kq * 4 + 2][m] = v.z;
            As[kq * 4 + 3][m] = v.w;
        }
#pragma unroll
        for (int i = 0; i < B4; i++) {
            int f = tid + i * 256;
            int kr = f / (BN / 4);
            int nq = f % (BN / 4);
            *(float4*)(&Bs[kr][nq * 4]) =
                *(const float4*)(W + (size_t)(kk + kr) * N + n0 + nq * 4);
        }
        __syncthreads();

#pragma unroll
        for (int k = 0; k < BK; k++) {
            float a[TM], b[TN];
#pragma unroll
            for (int i = 0; i < TM; i += 4)
                *(float4*)&a[i] = *(const float4*)&As[k][ty * TM + i];
#pragma unroll
            for (int j = 0; j < TN; j += 4)
                *(float4*)&b[j] = *(const float4*)&Bs[k][tx * TN + j];
#pragma unroll
            for (int i = 0; i < TM; i++)
#pragma unroll
                for (int j = 0; j < TN; j++)
                    acc[i][j] += a[i] * b[j];
        }
        __syncthreads();
    }

#pragma unroll
    for (int i = 0; i < TM; i++) {
        int row = m0 + ty * TM + i;
        if (row >= M) continue;
#pragma unroll
        for (int j = 0; j < TN; j += 4) {
            int col = n0 + tx * TN + j;
            float4 v;
            v.x = acc[i][j + 0];
            v.y = acc[i][j + 1];
            v.z = acc[i][j + 2];
            v.w = acc[i][j + 3];
            if (bias) {
                v.x += bias[col + 0];
                v.y += bias[col + 1];
                v.z += bias[col + 2];
                v.w += bias[col + 3];
            }
            if (RELU) {
                v.x = fmaxf(v.x, 0.f);
                v.y = fmaxf(v.y, 0.f);
                v.z = fmaxf(v.z, 0.f);
                v.w = fmaxf(v.w, 0.f);
            }
            *(float4*)(C + (size_t)row * ldc + col) = v;
        }
    }
}

// --------------------------- segmented gather-max ---------------------------
template<int NB>
__global__ void k_poolmax(const float* __restrict__ src, const int* __restrict__ idx,
                          float* __restrict__ dst)
{
    int g = blockIdx.x;
    __shared__ int sidx[NB];
    if (threadIdx.x < NB)
        sidx[threadIdx.x] = idx ? idx[g * NB + threadIdx.x] : g * NB + threadIdx.x;
    __syncthreads();
    int c = threadIdx.x * 4;
    float4 m = make_float4(-1e30f, -1e30f, -1e30f, -1e30f);
#pragma unroll
    for (int j = 0; j < NB; j++) {
        const float4 v = *(const float4*)(src + (size_t)sidx[j] * HIDW + c);
        m.x = fmaxf(m.x, v.x);
        m.y = fmaxf(m.y, v.y);
        m.z = fmaxf(m.z, v.z);
        m.w = fmaxf(m.w, v.w);
    }
    *(float4*)(dst + (size_t)g * HIDW + c) = m;
}

// -------------------- layer-1 combine + L2 normalize ------------------------
__global__ void k_final(const float* __restrict__ y0, const float* __restrict__ p2,
                        const float* __restrict__ Ws1, const float* __restrict__ Wn1,
                        float* __restrict__ out)
{
    int n = blockIdx.x;
    __shared__ float ss[256];
    __shared__ float sp[512];
    __shared__ float red[256];
    int tid = threadIdx.x;
    ss[tid] = y0[(size_t)n * 256 + tid];
    sp[tid] = p2[(size_t)n * 512 + tid];
    sp[256 + tid] = p2[(size_t)n * 512 + 256 + tid];
    __syncthreads();

    float acc = 0.f;
    if (tid < 128) {
#pragma unroll 8
        for (int k = 0; k < 256; k++) acc += ss[k] * Ws1[k * 128 + tid];
    } else {
        int c = tid - 128;
#pragma unroll 8
        for (int k = 0; k < 512; k++) acc += sp[k] * Wn1[k * 128 + c];
    }
    red[tid] = acc * acc;
    __syncthreads();
    for (int s = 128; s > 0; s >>= 1) {
        if (tid < s) red[tid] += red[tid + s];
        __syncthreads();
    }
    float inv = 1.f / fmaxf(sqrtf(red[0]), 1e-12f);
    out[(size_t)n * 256 + tid] = acc * inv;
}

// ------------------------------- launcher -----------------------------------
extern "C" void kernel_launch(void* const* d_in, const int* in_sizes, int n_in,
                              void* d_out, int out_size)
{
    (void)in_sizes; (void)n_in; (void)out_size;
    const int*   b1   = (const int*)d_in[0];
    const int*   b2   = (const int*)d_in[1];
    const float* feat = (const float*)d_in[2];
    const int*   adj  = (const int*)d_in[3];
    const float* Wp0  = (const float*)d_in[4];
    const float* bp0  = (const float*)d_in[5];
    const float* Wn0  = (const float*)d_in[6];
    const float* Ws0  = (const float*)d_in[7];
    const float* Wp1  = (const float*)d_in[8];
    const float* bp1  = (const float*)d_in[9];
    const float* Wn1  = (const float*)d_in[10];
    const float* Ws1  = (const float*)d_in[11];
    float* out = (float*)d_out;

    int *s1, *s2;
    float *H, *pool1, *pool0, *y1, *y0, *T, *pool2;
    cudaGetSymbolAddress((void**)&s1,    g_s1);
    cudaGetSymbolAddress((void**)&s2,    g_s2);
    cudaGetSymbolAddress((void**)&H,     g_H);
    cudaGetSymbolAddress((void**)&pool1, g_pool1);
    cudaGetSymbolAddress((void**)&pool0, g_pool0);
    cudaGetSymbolAddress((void**)&y1,    g_y1);
    cudaGetSymbolAddress((void**)&y0,    g_y0);
    cudaGetSymbolAddress((void**)&T,     g_T);
    cudaGetSymbolAddress((void**)&pool2, g_pool2);

    // 1) sampling
    k_sample1<<<(2 * N1 + 255) / 256, 256>>>(b1, b2, adj);
    k_sample2<<<(2 * N2 + 255) / 256, 256>>>(adj);

    // 2) H_all = relu(features @ W_pool0 + b_pool0)  [100000, 512]  (TF32 TC)
    k_gemm_tc<true><<<dim3((NN + 127) / 128, HIDW / 128), 256>>>(
        feat, nullptr, NN, FEAT, Wp0, HIDW, bp0, H, HIDW);

    for (int t = 0; t < 2; t++) {
        const int* bt = t ? b2 : b1;
        float* y1t = y1 + (size_t)t * N1 * 256;
        float* y0t = y0 + (size_t)t * BATCH * 256;
        float* p1t = pool1 + (size_t)t * N1 * HIDW;
        float* p0t = pool0 + (size_t)t * BATCH * HIDW;
        float* Tt  = T + (size_t)t * N1 * HIDW;
        float* p2t = pool2 + (size_t)t * BATCH * HIDW;

        // 3) segmented gather-max pools over H_all
        k_poolmax<NS_A><<<N1, 128>>>(H, s2 + (size_t)t * N2, p1t);
        k_poolmax<NS_B><<<BATCH, 128>>>(H, s1 + (size_t)t * N1, p0t);

        // 4) layer-0 combine (TF32 TC for the 5120-row GEMMs, SIMT for 512-row)
        k_gemm_tc<true><<<dim3(N1 / 128, 1), 256>>>(
            feat, s1 + (size_t)t * N1, N1, FEAT, Ws0, DOUT, nullptr, y1t, 256);
        k_gemm_tc<true><<<dim3(N1 / 128, 1), 256>>>(
            p1t, nullptr, N1, HIDW, Wn0, DOUT, nullptr, y1t + 128, 256);
        k_gemm<64, 128, 16, 4, 8, true><<<dim3(BATCH / 64, 1), 256>>>(
            feat, bt, BATCH, FEAT, Ws0, DOUT, nullptr, y0t, 256);
        k_gemm<64, 128, 16, 4, 8, true><<<dim3(BATCH / 64, 1), 256>>>(
            p0t, nullptr, BATCH, HIDW, Wn0, DOUT, nullptr, y0t + 128, 256);

        // 5) layer-1 pool MLP + consecutive segmax  (TF32 TC)
        k_gemm_tc<true><<<dim3(N1 / 128, HIDW / 128), 256>>>(
            y1t, nullptr, N1, 256, Wp1, HIDW, bp1, Tt, HIDW);
        k_poolmax<NS_B><<<BATCH, 128>>>(Tt, nullptr, p2t);

        // 6) final combine + L2 normalize (exact fp32)
        k_final<<<BATCH, 256>>>(y0t, p2t, Ws1, Wn1, out + (size_t)t * BATCH * 256);
    }
}

// round 4
// speedup vs baseline: 3.5323x; 2.0430x over previous
#include <cuda_runtime.h>
#include <cuda_fp16.h>
#include <cstdint>

// ---------------------------------------------------------------------------
// SampleAndAggregate (GraphSAGE, 2-layer maxpool)
// Round 4: fp16 mma.sync (m16n8k16) GEMMs, fp16-pretransposed weights,
//          batched tail launches. (tcgen05 unavailable: harness targets sm_100
//          without the 'a' feature suffix.)
// ---------------------------------------------------------------------------

#define BATCH 512
#define FEAT  256
#define HIDW  512
#define DOUT  128
#define DEG   128
#define NN    100000
#define NS_A  25
#define NS_B  10
#define N1    (BATCH*NS_B)     // 5120
#define N2    (N1*NS_A)        // 128000

// ------------------------- scratch (device globals) ------------------------
__device__ int    g_s1[2*N1];
__device__ int    g_s2[2*N2];
__device__ int    g_b12[2*BATCH];
__device__ __half g_Wp0t[HIDW*FEAT];   // [512][256]
__device__ __half g_Wn0t[DOUT*HIDW];   // [128][512]
__device__ __half g_Ws0t[DOUT*FEAT];   // [128][256]
__device__ __half g_Wp1t[HIDW*2*DOUT]; // [512][256]
__device__ float  g_H[(size_t)NN*HIDW];
__device__ float  g_pool1[2*(size_t)N1*HIDW];
__device__ float  g_pool0[2*(size_t)BATCH*HIDW];
__device__ float  g_y1[2*(size_t)N1*2*DOUT];
__device__ float  g_y0[2*(size_t)BATCH*2*DOUT];
__device__ float  g_T[2*(size_t)N1*HIDW];
__device__ float  g_pool2[2*(size_t)BATCH*HIDW];

// ------------------------------- sampling ----------------------------------
__global__ void k_sample1(const int* __restrict__ b1, const int* __restrict__ b2,
                          const int* __restrict__ adj) {
    int i = blockIdx.x * blockDim.x + threadIdx.x;
    if (i >= 2 * N1) return;
    int t = i / N1, r = i % N1;
    int n = r / NS_B, j = r % NS_B;
    int node = (t ? b2 : b1)[n];
    if (j == 0) g_b12[t * BATCH + n] = node;
    g_s1[t * N1 + r] = adj[(size_t)node * DEG + j];
}
__global__ void k_sample2(const int* __restrict__ adj) {
    int i = blockIdx.x * blockDim.x + threadIdx.x;
    if (i >= 2 * N2) return;
    int t = i / N2, r = i % N2;
    int n = r / NS_A, j = r % NS_A;
    int parent = g_s1[t * N1 + n];
    g_s2[t * N2 + r] = adj[(size_t)parent * DEG + j];
}

// ------------------- transpose + fp16 convert: W[K][N] -> out[N][K] --------
__global__ void k_trc(const float* __restrict__ W, __half* __restrict__ out,
                      int K, int N) {
    __shared__ float t[32][33];
    int n0 = blockIdx.x * 32, k0 = blockIdx.y * 32;
    for (int i = threadIdx.y; i < 32; i += 8)
        t[i][threadIdx.x] = W[(size_t)(k0 + i) * N + n0 + threadIdx.x];
    __syncthreads();
    for (int i = threadIdx.y; i < 32; i += 8)
        out[(size_t)(n0 + i) * K + k0 + threadIdx.x] =
            __float2half_rn(t[threadIdx.x][i]);
}

// ----------------------------- fp16 MMA GEMM --------------------------------
// C[row, 0:BN*gy] = act((gather? A[gidx[row]] : A[row]) @ Bt^T + bias)
// A: f32 [*, K] row-major (K-contig). Bt: fp16 [N][K] (K-contig).
// BM=128, BN=128, BK=32. 256 thr = 8 warps (2m x 4n), warp tile 64x32.
__device__ __forceinline__ void mma_f16(float c[4], uint32_t a0, uint32_t a1,
                                        uint32_t a2, uint32_t a3,
                                        uint32_t b0, uint32_t b1) {
    asm volatile(
        "mma.sync.aligned.m16n8k16.row.col.f32.f16.f16.f32 "
        "{%0,%1,%2,%3}, {%4,%5,%6,%7}, {%8,%9}, {%0,%1,%2,%3};"
        : "+f"(c[0]), "+f"(c[1]), "+f"(c[2]), "+f"(c[3])
        : "r"(a0), "r"(a1), "r"(a2), "r"(a3), "r"(b0), "r"(b1));
}

template<bool RELU>
__global__ __launch_bounds__(256)
void k_gemm_f16(const float* __restrict__ A, const int* __restrict__ gidx,
                int M, int K,
                const __half* __restrict__ Bt, int N,
                const float* __restrict__ bias,
                float* __restrict__ C, int ldc)
{
    constexpr int BM = 128, BK = 32;
    constexpr int LDSH = BK + 8;                 // 40 halves / row (80B)
    __shared__ __align__(16) __half As[2][BM][LDSH];
    __shared__ __align__(16) __half Bs[2][128][LDSH];

    const int tid  = threadIdx.x;
    const int lane = tid & 31;
    const int warp = tid >> 5;
    const int wm = warp >> 2, wn = warp & 3;
    const int m0g = blockIdx.x * BM;
    const int n0g = blockIdx.y * 128;

    float acc[4][4][4];
#pragma unroll
    for (int i = 0; i < 4; i++)
#pragma unroll
        for (int j = 0; j < 4; j++)
#pragma unroll
            for (int r = 0; r < 4; r++) acc[i][j][r] = 0.f;

    // staging regs: per i, one 8-half unit for A (from 2 float4) and B (uint4)
    float4 av[2][2];
    uint4  bv[2];

    auto load_regs = [&](int kk) {
#pragma unroll
        for (int i = 0; i < 2; i++) {
            int f = tid + i * 256;               // 0..511
            int m = f >> 2, u = f & 3;           // row, 8-k unit
            int row = m0g + m;
            float4 z = make_float4(0.f, 0.f, 0.f, 0.f);
            if (row < M) {
                int r = gidx ? gidx[row] : row;
                const float* p = A + (size_t)r * K + kk + u * 8;
                av[i][0] = *(const float4*)p;
                av[i][1] = *(const float4*)(p + 4);
            } else { av[i][0] = z; av[i][1] = z; }
            bv[i] = *(const uint4*)(Bt + (size_t)(n0g + m) * K + kk + u * 8);
        }
    };
    auto store_smem = [&](int buf) {
#pragma unroll
        for (int i = 0; i < 2; i++) {
            int f = tid + i * 256;
            int m = f >> 2, u = f & 3;
            __half2 h[4];
            h[0] = __floats2half2_rn(av[i][0].x, av[i][0].y);
            h[1] = __floats2half2_rn(av[i][0].z, av[i][0].w);
            h[2] = __floats2half2_rn(av[i][1].x, av[i][1].y);
            h[3] = __floats2half2_rn(av[i][1].z, av[i][1].w);
            *(uint4*)&As[buf][m][u * 8] = *(uint4*)h;
            *(uint4*)&Bs[buf][m][u * 8] = bv[i];
        }
    };

    const int m_base = wm * 64, n_base = wn * 32;
    const int rql = lane >> 2;   // 0..7
    const int cql = lane & 3;    // 0..3

    load_regs(0);
    store_smem(0);
    __syncthreads();

    int buf = 0;
    const int ktiles = K / BK;
    for (int kt = 0; kt < ktiles; kt++) {
        if (kt + 1 < ktiles) load_regs((kt + 1) * BK);

#pragma unroll
        for (int k0 = 0; k0 < BK; k0 += 16) {
            uint32_t af[4][4], bf[4][2];
#pragma unroll
            for (int mt = 0; mt < 4; mt++) {
                int r = m_base + mt * 16 + rql;
                af[mt][0] = *(const uint32_t*)&As[buf][r][k0 + 2 * cql];
                af[mt][1] = *(const uint32_t*)&As[buf][r + 8][k0 + 2 * cql];
                af[mt][2] = *(const uint32_t*)&As[buf][r][k0 + 2 * cql + 8];
                af[mt][3] = *(const uint32_t*)&As[buf][r + 8][k0 + 2 * cql + 8];
            }
#pragma unroll
            for (int nt = 0; nt < 4; nt++) {
                int c = n_base + nt * 8 + rql;
                bf[nt][0] = *(const uint32_t*)&Bs[buf][c][k0 + 2 * cql];
                bf[nt][1] = *(const uint32_t*)&Bs[buf][c][k0 + 2 * cql + 8];
            }
#pragma unroll
            for (int mt = 0; mt < 4; mt++)
#pragma unroll
                for (int nt = 0; nt < 4; nt++)
                    mma_f16(acc[mt][nt], af[mt][0], af[mt][1], af[mt][2],
                            af[mt][3], bf[nt][0], bf[nt][1]);
        }

        if (kt + 1 < ktiles) {
            store_smem(buf ^ 1);
            __syncthreads();
            buf ^= 1;
        }
    }

    // epilogue (same accumulator layout as tf32 path)
#pragma unroll
    for (int mt = 0; mt < 4; mt++) {
#pragma unroll
        for (int half = 0; half < 2; half++) {
            int row = m0g + m_base + mt * 16 + rql + half * 8;
            if (row >= M) continue;
#pragma unroll
            for (int nt = 0; nt < 4; nt++) {
                int col = n0g + n_base + nt * 8 + cql * 2;
                float2 v;
                v.x = acc[mt][nt][half * 2 + 0];
                v.y = acc[mt][nt][half * 2 + 1];
                if (bias) { v.x += bias[col]; v.y += bias[col + 1]; }
                if (RELU) { v.x = fmaxf(v.x, 0.f); v.y = fmaxf(v.y, 0.f); }
                *(float2*)(C + (size_t)row * ldc + col) = v;
            }
        }
    }
}

// --------------------------- segmented gather-max ---------------------------
template<int NB>
__global__ void k_poolmax(const float* __restrict__ src, const int* __restrict__ idx,
                          float* __restrict__ dst)
{
    int g = blockIdx.x;
    __shared__ int sidx[NB];
    if (threadIdx.x < NB)
        sidx[threadIdx.x] = idx ? idx[g * NB + threadIdx.x] : g * NB + threadIdx.x;
    __syncthreads();
    int c = threadIdx.x * 4;
    float4 m = make_float4(-1e30f, -1e30f, -1e30f, -1e30f);
#pragma unroll
    for (int j = 0; j < NB; j++) {
        const float4 v = *(const float4*)(src + (size_t)sidx[j] * HIDW + c);
        m.x = fmaxf(m.x, v.x);
        m.y = fmaxf(m.y, v.y);
        m.z = fmaxf(m.z, v.z);
        m.w = fmaxf(m.w, v.w);
    }
    *(float4*)(dst + (size_t)g * HIDW + c) = m;
}

// -------------------- layer-1 combine + L2 normalize ------------------------
__global__ void k_final(const float* __restrict__ y0, const float* __restrict__ p2,
                        const float* __restrict__ Ws1, const float* __restrict__ Wn1,
                        float* __restrict__ out)
{
    int n = blockIdx.x;
    __shared__ float ss[256];
    __shared__ float sp[512];
    __shared__ float red[256];
    int tid = threadIdx.x;
    ss[tid] = y0[(size_t)n * 256 + tid];
    sp[tid] = p2[(size_t)n * 512 + tid];
    sp[256 + tid] = p2[(size_t)n * 512 + 256 + tid];
    __syncthreads();

    float acc = 0.f;
    if (tid < 128) {
#pragma unroll 8
        for (int k = 0; k < 256; k++) acc += ss[k] * Ws1[k * 128 + tid];
    } else {
        int c = tid - 128;
#pragma unroll 8
        for (int k = 0; k < 512; k++) acc += sp[k] * Wn1[k * 128 + c];
    }
    red[tid] = acc * acc;
    __syncthreads();
    for (int s = 128; s > 0; s >>= 1) {
        if (tid < s) red[tid] += red[tid + s];
        __syncthreads();
    }
    float inv = 1.f / fmaxf(sqrtf(red[0]), 1e-12f);
    out[(size_t)n * 256 + tid] = acc * inv;
}

// ------------------------------- launcher -----------------------------------
extern "C" void kernel_launch(void* const* d_in, const int* in_sizes, int n_in,
                              void* d_out, int out_size)
{
    (void)in_sizes; (void)n_in; (void)out_size;
    const int*   b1   = (const int*)d_in[0];
    const int*   b2   = (const int*)d_in[1];
    const float* feat = (const float*)d_in[2];
    const int*   adj  = (const int*)d_in[3];
    const float* Wp0  = (const float*)d_in[4];
    const float* bp0  = (const float*)d_in[5];
    const float* Wn0  = (const float*)d_in[6];
    const float* Ws0  = (const float*)d_in[7];
    const float* Wp1  = (const float*)d_in[8];
    const float* bp1  = (const float*)d_in[9];
    const float* Wn1  = (const float*)d_in[10];
    const float* Ws1  = (const float*)d_in[11];
    float* out = (float*)d_out;

    int *s1, *s2, *b12;
    float *H, *pool1, *pool0, *y1, *y0, *T, *pool2;
    __half *Wp0t, *Wn0t, *Ws0t, *Wp1t;
    cudaGetSymbolAddress((void**)&s1,    g_s1);
    cudaGetSymbolAddress((void**)&s2,    g_s2);
    cudaGetSymbolAddress((void**)&b12,   g_b12);
    cudaGetSymbolAddress((void**)&H,     g_H);
    cudaGetSymbolAddress((void**)&pool1, g_pool1);
    cudaGetSymbolAddress((void**)&pool0, g_pool0);
    cudaGetSymbolAddress((void**)&y1,    g_y1);
    cudaGetSymbolAddress((void**)&y0,    g_y0);
    cudaGetSymbolAddress((void**)&T,     g_T);
    cudaGetSymbolAddress((void**)&pool2, g_pool2);
    cudaGetSymbolAddress((void**)&Wp0t,  g_Wp0t);
    cudaGetSymbolAddress((void**)&Wn0t,  g_Wn0t);
    cudaGetSymbolAddress((void**)&Ws0t,  g_Ws0t);
    cudaGetSymbolAddress((void**)&Wp1t,  g_Wp1t);

    // 1) sampling + weight transpose/convert (fp16 [N][K])
    k_sample1<<<(2 * N1 + 255) / 256, 256>>>(b1, b2, adj);
    k_sample2<<<(2 * N2 + 255) / 256, 256>>>(adj);
    k_trc<<<dim3(HIDW / 32, FEAT / 32),  dim3(32, 8)>>>(Wp0, Wp0t, FEAT, HIDW);
    k_trc<<<dim3(DOUT / 32, HIDW / 32),  dim3(32, 8)>>>(Wn0, Wn0t, HIDW, DOUT);
    k_trc<<<dim3(DOUT / 32, FEAT / 32),  dim3(32, 8)>>>(Ws0, Ws0t, FEAT, DOUT);
    k_trc<<<dim3(HIDW / 32, FEAT / 32),  dim3(32, 8)>>>(Wp1, Wp1t, FEAT, HIDW);

    // 2) H_all = relu(features @ W_pool0 + b_pool0)  [100000, 512]
    k_gemm_f16<true><<<dim3((NN + 127) / 128, HIDW / 128), 256>>>(
        feat, nullptr, NN, FEAT, Wp0t, HIDW, bp0, H, HIDW);

    // 3) segmented gather-max pools over H_all (both batches at once)
    k_poolmax<NS_A><<<2 * N1, 128>>>(H, s2, pool1);
    k_poolmax<NS_B><<<2 * BATCH, 128>>>(H, s1, pool0);

    // 4) layer-0 combine (relu distributes over concat)
    k_gemm_f16<true><<<dim3(2 * N1 / 128, 1), 256>>>(
        feat, s1, 2 * N1, FEAT, Ws0t, DOUT, nullptr, y1, 256);
    k_gemm_f16<true><<<dim3(2 * N1 / 128, 1), 256>>>(
        pool1, nullptr, 2 * N1, HIDW, Wn0t, DOUT, nullptr, y1 + 128, 256);
    k_gemm_f16<true><<<dim3(2 * BATCH / 128, 1), 256>>>(
        feat, b12, 2 * BATCH, FEAT, Ws0t, DOUT, nullptr, y0, 256);
    k_gemm_f16<true><<<dim3(2 * BATCH / 128, 1), 256>>>(
        pool0, nullptr, 2 * BATCH, HIDW, Wn0t, DOUT, nullptr, y0 + 128, 256);

    // 5) layer-1 pool MLP + consecutive segmax
    k_gemm_f16<true><<<dim3(2 * N1 / 128, HIDW / 128), 256>>>(
        y1, nullptr, 2 * N1, 256, Wp1t, HIDW, bp1, T, HIDW);
    k_poolmax<NS_B><<<2 * BATCH, 128>>>(T, nullptr, pool2);

    // 6) final combine + L2 normalize (exact fp32)
    k_final<<<2 * BATCH, 256>>>(y0, pool2, Ws1, Wn1, out);
}

// round 5
// speedup vs baseline: 4.0269x; 1.1400x over previous
#include <cuda_runtime.h>
#include <cuda_fp16.h>
#include <cstdint>

// ---------------------------------------------------------------------------
// SampleAndAggregate (GraphSAGE, 2-layer maxpool)
// Round 5: fp16 intermediate storage (H/pool1/pool0/y1 — provably identical
//          to fp32-store-then-convert), ldmatrix fragment loads in GEMMs.
// ---------------------------------------------------------------------------

#define BATCH 512
#define FEAT  256
#define HIDW  512
#define DOUT  128
#define DEG   128
#define NN    100000
#define NS_A  25
#define NS_B  10
#define N1    (BATCH*NS_B)     // 5120
#define N2    (N1*NS_A)        // 128000

// ------------------------- scratch (device globals) ------------------------
__device__ int    g_s1[2*N1];
__device__ int    g_s2[2*N2];
__device__ int    g_b12[2*BATCH];
__device__ __half g_Wp0t[HIDW*FEAT];   // [512][256]
__device__ __half g_Wn0t[DOUT*HIDW];   // [128][512]
__device__ __half g_Ws0t[DOUT*FEAT];   // [128][256]
__device__ __half g_Wp1t[HIDW*2*DOUT]; // [512][256]
__device__ __half g_H[(size_t)NN*HIDW];            // fp16 now (102 MB)
__device__ __half g_pool1[2*(size_t)N1*HIDW];
__device__ __half g_pool0[2*(size_t)BATCH*HIDW];
__device__ __half g_y1[2*(size_t)N1*2*DOUT];
__device__ float  g_y0[2*(size_t)BATCH*2*DOUT];
__device__ float  g_T[2*(size_t)N1*HIDW];
__device__ float  g_pool2[2*(size_t)BATCH*HIDW];

// ------------------------------- sampling ----------------------------------
__global__ void k_sample1(const int* __restrict__ b1, const int* __restrict__ b2,
                          const int* __restrict__ adj) {
    int i = blockIdx.x * blockDim.x + threadIdx.x;
    if (i >= 2 * N1) return;
    int t = i / N1, r = i % N1;
    int n = r / NS_B, j = r % NS_B;
    int node = (t ? b2 : b1)[n];
    if (j == 0) g_b12[t * BATCH + n] = node;
    g_s1[t * N1 + r] = adj[(size_t)node * DEG + j];
}
__global__ void k_sample2(const int* __restrict__ adj) {
    int i = blockIdx.x * blockDim.x + threadIdx.x;
    if (i >= 2 * N2) return;
    int t = i / N2, r = i % N2;
    int n = r / NS_A, j = r % NS_A;
    int parent = g_s1[t * N1 + n];
    g_s2[t * N2 + r] = adj[(size_t)parent * DEG + j];
}

// ------------------- transpose + fp16 convert: W[K][N] -> out[N][K] --------
__global__ void k_trc(const float* __restrict__ W, __half* __restrict__ out,
                      int K, int N) {
    __shared__ float t[32][33];
    int n0 = blockIdx.x * 32, k0 = blockIdx.y * 32;
    for (int i = threadIdx.y; i < 32; i += 8)
        t[i][threadIdx.x] = W[(size_t)(k0 + i) * N + n0 + threadIdx.x];
    __syncthreads();
    for (int i = threadIdx.y; i < 32; i += 8)
        out[(size_t)(n0 + i) * K + k0 + threadIdx.x] =
            __float2half_rn(t[threadIdx.x][i]);
}

// ----------------------------- fp16 MMA GEMM --------------------------------
__device__ __forceinline__ void mma_f16(float c[4], uint32_t a0, uint32_t a1,
                                        uint32_t a2, uint32_t a3,
                                        uint32_t b0, uint32_t b1) {
    asm volatile(
        "mma.sync.aligned.m16n8k16.row.col.f32.f16.f16.f32 "
        "{%0,%1,%2,%3}, {%4,%5,%6,%7}, {%8,%9}, {%0,%1,%2,%3};"
        : "+f"(c[0]), "+f"(c[1]), "+f"(c[2]), "+f"(c[3])
        : "r"(a0), "r"(a1), "r"(a2), "r"(a3), "r"(b0), "r"(b1));
}
__device__ __forceinline__ void ldsm_x4(uint32_t& r0, uint32_t& r1,
                                        uint32_t& r2, uint32_t& r3,
                                        uint32_t addr) {
    asm volatile("ldmatrix.sync.aligned.m8n8.x4.shared.b16 {%0,%1,%2,%3}, [%4];"
                 : "=r"(r0), "=r"(r1), "=r"(r2), "=r"(r3) : "r"(addr));
}
__device__ __forceinline__ uint32_t smem_u32(const void* p) {
    return (uint32_t)__cvta_generic_to_shared(p);
}

// A: AT (float or __half) [*, K] K-contig. Bt: fp16 [N][K] K-contig.
// BM=128, BN=128, BK=32; 256 thr = 8 warps (2m x 4n), warp tile 64x32.
template<typename AT, bool OUTH, bool RELU>
__global__ __launch_bounds__(256)
void k_gemm_f16(const AT* __restrict__ A, const int* __restrict__ gidx,
                int M, int K,
                const __half* __restrict__ Bt,
                const float* __restrict__ bias,
                void* __restrict__ Cv, int ldc)
{
    constexpr bool AF32 = (sizeof(AT) == 4);
    constexpr int BM = 128, BK = 32;
    constexpr int LDSH = BK + 8;                 // 40 halves (80B) / row
    constexpr uint32_t BUFB = BM * LDSH * 2;     // bytes per buffer
    __shared__ __align__(16) __half As[2][BM][LDSH];
    __shared__ __align__(16) __half Bs[2][128][LDSH];

    const int tid  = threadIdx.x;
    const int lane = tid & 31;
    const int warp = tid >> 5;
    const int wm = warp >> 2, wn = warp & 3;
    const int m0g = blockIdx.x * BM;
    const int n0g = blockIdx.y * 128;

    float acc[4][4][4];
#pragma unroll
    for (int i = 0; i < 4; i++)
#pragma unroll
        for (int j = 0; j < 4; j++)
#pragma unroll
            for (int r = 0; r < 4; r++) acc[i][j][r] = 0.f;

    float4 av[2][2];
    uint4  ah[2];
    uint4  bv[2];

    auto load_regs = [&](int kk) {
#pragma unroll
        for (int i = 0; i < 2; i++) {
            int f = tid + i * 256;               // 0..511
            int m = f >> 2, u = f & 3;           // row, 8-half k unit
            int row = m0g + m;
            if (AF32) {
                float4 z = make_float4(0.f, 0.f, 0.f, 0.f);
                if (row < M) {
                    int r = gidx ? gidx[row] : row;
                    const float* p = (const float*)A + (size_t)r * K + kk + u * 8;
                    av[i][0] = *(const float4*)p;
                    av[i][1] = *(const float4*)(p + 4);
                } else { av[i][0] = z; av[i][1] = z; }
            } else {
                if (row < M) {
                    int r = gidx ? gidx[row] : row;
                    ah[i] = *(const uint4*)((const __half*)A + (size_t)r * K + kk + u * 8);
                } else ah[i] = make_uint4(0, 0, 0, 0);
            }
            bv[i] = *(const uint4*)(Bt + (size_t)(n0g + m) * K + kk + u * 8);
        }
    };
    auto store_smem = [&](int buf) {
#pragma unroll
        for (int i = 0; i < 2; i++) {
            int f = tid + i * 256;
            int m = f >> 2, u = f & 3;
            if (AF32) {
                __half2 h[4];
                h[0] = __floats2half2_rn(av[i][0].x, av[i][0].y);
                h[1] = __floats2half2_rn(av[i][0].z, av[i][0].w);
                h[2] = __floats2half2_rn(av[i][1].x, av[i][1].y);
                h[3] = __floats2half2_rn(av[i][1].z, av[i][1].w);
                *(uint4*)&As[buf][m][u * 8] = *(uint4*)h;
            } else {
                *(uint4*)&As[buf][m][u * 8] = ah[i];
            }
            *(uint4*)&Bs[buf][m][u * 8] = bv[i];
        }
    };

    const int m_base = wm * 64, n_base = wn * 32;
    const int rql = lane >> 2;   // 0..7
    const int cql = lane & 3;    // 0..3

    // ldmatrix lane addresses (byte offsets within one buffer)
    const uint32_t as0 = smem_u32(&As[0][0][0]);
    const uint32_t bs0 = smem_u32(&Bs[0][0][0]);
    uint32_t aoff[4], boff[2];
#pragma unroll
    for (int mt = 0; mt < 4; mt++)
        aoff[mt] = ((m_base + mt * 16 + (lane & 15)) * LDSH + (lane >> 4) * 8) * 2;
#pragma unroll
    for (int p = 0; p < 2; p++) {
        int rowb = n_base + p * 16 + ((lane >> 4) & 1) * 8 + (lane & 7);
        boff[p] = (rowb * LDSH + ((lane >> 3) & 1) * 8) * 2;
    }

    load_regs(0);
    store_smem(0);
    __syncthreads();

    int buf = 0;
    const int ktiles = K / BK;
    for (int kt = 0; kt < ktiles; kt++) {
        if (kt + 1 < ktiles) load_regs((kt + 1) * BK);

#pragma unroll
        for (int k0 = 0; k0 < BK; k0 += 16) {
            uint32_t af[4][4], bf[4][2];
            const uint32_t ab = as0 + buf * BUFB + k0 * 2;
            const uint32_t bb = bs0 + buf * BUFB + k0 * 2;
#pragma unroll
            for (int mt = 0; mt < 4; mt++)
                ldsm_x4(af[mt][0], af[mt][1], af[mt][2], af[mt][3], ab + aoff[mt]);
#pragma unroll
            for (int p = 0; p < 2; p++)
                ldsm_x4(bf[2 * p][0], bf[2 * p][1], bf[2 * p + 1][0],
                        bf[2 * p + 1][1], bb + boff[p]);
#pragma unroll
            for (int mt = 0; mt < 4; mt++)
#pragma unroll
                for (int nt = 0; nt < 4; nt++)
                    mma_f16(acc[mt][nt], af[mt][0], af[mt][1], af[mt][2],
                            af[mt][3], bf[nt][0], bf[nt][1]);
        }

        if (kt + 1 < ktiles) {
            store_smem(buf ^ 1);
            __syncthreads();
            buf ^= 1;
        }
    }

    // epilogue
#pragma unroll
    for (int mt = 0; mt < 4; mt++) {
#pragma unroll
        for (int half = 0; half < 2; half++) {
            int row = m0g + m_base + mt * 16 + rql + half * 8;
            if (row >= M) continue;
#pragma unroll
            for (int nt = 0; nt < 4; nt++) {
                int col = n0g + n_base + nt * 8 + cql * 2;
                float2 v;
                v.x = acc[mt][nt][half * 2 + 0];
                v.y = acc[mt][nt][half * 2 + 1];
                if (bias) { v.x += bias[col]; v.y += bias[col + 1]; }
                if (RELU) { v.x = fmaxf(v.x, 0.f); v.y = fmaxf(v.y, 0.f); }
                if (OUTH) {
                    *(__half2*)((__half*)Cv + (size_t)row * ldc + col) =
                        __floats2half2_rn(v.x, v.y);
                } else {
                    *(float2*)((float*)Cv + (size_t)row * ldc + col) = v;
                }
            }
        }
    }
}

// --------------------- segmented gather-max (fp16) --------------------------
// values are post-relu (>=0) so init 0 is exact; round(max)=max(round).
template<int NB>
__global__ void k_poolmax_h(const __half* __restrict__ src,
                            const int* __restrict__ idx,
                            __half* __restrict__ dst)
{
    int g = blockIdx.x;
    __shared__ int sidx[NB];
    if (threadIdx.x < NB)
        sidx[threadIdx.x] = idx ? idx[g * NB + threadIdx.x] : g * NB + threadIdx.x;
    __syncthreads();
    int c = threadIdx.x * 8;     // 64 threads x 8 halves = 512 cols
    __half2 m0 = __float2half2_rn(0.f), m1 = m0, m2 = m0, m3 = m0;
#pragma unroll
    for (int j = 0; j < NB; j++) {
        uint4 v = *(const uint4*)(src + (size_t)sidx[j] * HIDW + c);
        const __half2* h = (const __half2*)&v;
        m0 = __hmax2(m0, h[0]);
        m1 = __hmax2(m1, h[1]);
        m2 = __hmax2(m2, h[2]);
        m3 = __hmax2(m3, h[3]);
    }
    __half2 r[4] = { m0, m1, m2, m3 };
    *(uint4*)(dst + (size_t)g * HIDW + c) = *(uint4*)r;
}

// --------------------- segmented max (fp32, consecutive) --------------------
template<int NB>
__global__ void k_poolmax_f(const float* __restrict__ src, float* __restrict__ dst)
{
    int g = blockIdx.x;
    int c = threadIdx.x * 4;     // 128 threads x 4 = 512
    float4 m = make_float4(-1e30f, -1e30f, -1e30f, -1e30f);
#pragma unroll
    for (int j = 0; j < NB; j++) {
        const float4 v = *(const float4*)(src + (size_t)(g * NB + j) * HIDW + c);
        m.x = fmaxf(m.x, v.x);
        m.y = fmaxf(m.y, v.y);
        m.z = fmaxf(m.z, v.z);
        m.w = fmaxf(m.w, v.w);
    }
    *(float4*)(dst + (size_t)g * HIDW + c) = m;
}

// -------------------- layer-1 combine + L2 normalize ------------------------
__global__ void k_final(const float* __restrict__ y0, const float* __restrict__ p2,
                        const float* __restrict__ Ws1, const float* __restrict__ Wn1,
                        float* __restrict__ out)
{
    int n = blockIdx.x;
    __shared__ float ss[256];
    __shared__ float sp[512];
    __shared__ float red[256];
    int tid = threadIdx.x;
    ss[tid] = y0[(size_t)n * 256 + tid];
    sp[tid] = p2[(size_t)n * 512 + tid];
    sp[256 + tid] = p2[(size_t)n * 512 + 256 + tid];
    __syncthreads();

    float acc = 0.f;
    if (tid < 128) {
#pragma unroll 8
        for (int k = 0; k < 256; k++) acc += ss[k] * Ws1[k * 128 + tid];
    } else {
        int c = tid - 128;
#pragma unroll 8
        for (int k = 0; k < 512; k++) acc += sp[k] * Wn1[k * 128 + c];
    }
    red[tid] = acc * acc;
    __syncthreads();
    for (int s = 128; s > 0; s >>= 1) {
        if (tid < s) red[tid] += red[tid + s];
        __syncthreads();
    }
    float inv = 1.f / fmaxf(sqrtf(red[0]), 1e-12f);
    out[(size_t)n * 256 + tid] = acc * inv;
}

// ------------------------------- launcher -----------------------------------
extern "C" void kernel_launch(void* const* d_in, const int* in_sizes, int n_in,
                              void* d_out, int out_size)
{
    (void)in_sizes; (void)n_in; (void)out_size;
    const int*   b1   = (const int*)d_in[0];
    const int*   b2   = (const int*)d_in[1];
    const float* feat = (const float*)d_in[2];
    const int*   adj  = (const int*)d_in[3];
    const float* Wp0  = (const float*)d_in[4];
    const float* bp0  = (const float*)d_in[5];
    const float* Wn0  = (const float*)d_in[6];
    const float* Ws0  = (const float*)d_in[7];
    const float* Wp1  = (const float*)d_in[8];
    const float* bp1  = (const float*)d_in[9];
    const float* Wn1  = (const float*)d_in[10];
    const float* Ws1  = (const float*)d_in[11];
    float* out = (float*)d_out;

    int *s1, *s2, *b12;
    __half *H, *pool1, *pool0, *y1, *Wp0t, *Wn0t, *Ws0t, *Wp1t;
    float *y0, *T, *pool2;
    cudaGetSymbolAddress((void**)&s1,    g_s1);
    cudaGetSymbolAddress((void**)&s2,    g_s2);
    cudaGetSymbolAddress((void**)&b12,   g_b12);
    cudaGetSymbolAddress((void**)&H,     g_H);
    cudaGetSymbolAddress((void**)&pool1, g_pool1);
    cudaGetSymbolAddress((void**)&pool0, g_pool0);
    cudaGetSymbolAddress((void**)&y1,    g_y1);
    cudaGetSymbolAddress((void**)&y0,    g_y0);
    cudaGetSymbolAddress((void**)&T,     g_T);
    cudaGetSymbolAddress((void**)&pool2, g_pool2);
    cudaGetSymbolAddress((void**)&Wp0t,  g_Wp0t);
    cudaGetSymbolAddress((void**)&Wn0t,  g_Wn0t);
    cudaGetSymbolAddress((void**)&Ws0t,  g_Ws0t);
    cudaGetSymbolAddress((void**)&Wp1t,  g_Wp1t);

    // 1) sampling + weight transpose/convert (fp16 [N][K])
    k_sample1<<<(2 * N1 + 255) / 256, 256>>>(b1, b2, adj);
    k_sample2<<<(2 * N2 + 255) / 256, 256>>>(adj);
    k_trc<<<dim3(HIDW / 32, FEAT / 32),  dim3(32, 8)>>>(Wp0, Wp0t, FEAT, HIDW);
    k_trc<<<dim3(DOUT / 32, HIDW / 32),  dim3(32, 8)>>>(Wn0, Wn0t, HIDW, DOUT);
    k_trc<<<dim3(DOUT / 32, FEAT / 32),  dim3(32, 8)>>>(Ws0, Ws0t, FEAT, DOUT);
    k_trc<<<dim3(HIDW / 32, FEAT / 32),  dim3(32, 8)>>>(Wp1, Wp1t, FEAT, HIDW);

    // 2) H_all = relu(features @ W_pool0 + b)  [100000, 512] fp16 out
    k_gemm_f16<float, true, true><<<dim3((NN + 127) / 128, HIDW / 128), 256>>>(
        feat, nullptr, NN, FEAT, Wp0t, bp0, H, HIDW);

    // 3) segmented gather-max pools over H (fp16, both batches at once)
    k_poolmax_h<NS_A><<<2 * N1, 64>>>(H, s2, pool1);
    k_poolmax_h<NS_B><<<2 * BATCH, 64>>>(H, s1, pool0);

    // 4) layer-0 combine (relu distributes over concat)
    k_gemm_f16<float, true, true><<<dim3(2 * N1 / 128, 1), 256>>>(
        feat, s1, 2 * N1, FEAT, Ws0t, nullptr, y1, 256);
    k_gemm_f16<__half, true, true><<<dim3(2 * N1 / 128, 1), 256>>>(
        pool1, nullptr, 2 * N1, HIDW, Wn0t, nullptr, y1 + 128, 256);
    k_gemm_f16<float, false, true><<<dim3(2 * BATCH / 128, 1), 256>>>(
        feat, b12, 2 * BATCH, FEAT, Ws0t, nullptr, y0, 256);
    k_gemm_f16<__half, false, true><<<dim3(2 * BATCH / 128, 1), 256>>>(
        pool0, nullptr, 2 * BATCH, HIDW, Wn0t, nullptr, y0 + 128, 256);

    // 5) layer-1 pool MLP (A = y1 fp16) + consecutive segmax (fp32)
    k_gemm_f16<__half, false, true><<<dim3(2 * N1 / 128, HIDW / 128), 256>>>(
        y1, nullptr, 2 * N1, 2 * DOUT, Wp1t, bp1, T, HIDW);
    k_poolmax_f<NS_B><<<2 * BATCH, 128>>>(T, pool2);

    // 6) final combine + L2 normalize (exact fp32)
    k_final<<<2 * BATCH, 256>>>(y0, pool2, Ws1, Wn1, out);
}

// round 7
// speedup vs baseline: 4.4104x; 1.0952x over previous
#include <cuda_runtime.h>
#include <cuda_fp16.h>
#include <cstdint>

// ---------------------------------------------------------------------------
// SampleAndAggregate (GraphSAGE, 2-layer maxpool)
// Round 7: R6 pipeline with the tail-sync fix (wait_group 0 on final tiles —
//          R6 raced on the last k-tile). fp16 features, fused weight prep.
// ---------------------------------------------------------------------------

#define BATCH 512
#define FEAT  256
#define HIDW  512
#define DOUT  128
#define DEG   128
#define NN    100000
#define NS_A  25
#define NS_B  10
#define N1    (BATCH*NS_B)     // 5120
#define N2    (N1*NS_A)        // 128000

// ------------------------- scratch (device globals) ------------------------
__device__ int    g_s1[2*N1];
__device__ int    g_s2[2*N2];
__device__ int    g_b12[2*BATCH];
__device__ __half g_featH[(size_t)NN*FEAT];        // fp16 features (51 MB)
__device__ __half g_Wp0t[HIDW*FEAT];   // [512][256]
__device__ __half g_Wn0t[DOUT*HIDW];   // [128][512]
__device__ __half g_Ws0t[DOUT*FEAT];   // [128][256]
__device__ __half g_Wp1t[HIDW*2*DOUT]; // [512][256]
__device__ __half g_H[(size_t)NN*HIDW];            // fp16 (102 MB)
__device__ __half g_pool1[2*(size_t)N1*HIDW];
__device__ __half g_pool0[2*(size_t)BATCH*HIDW];
__device__ __half g_y1[2*(size_t)N1*2*DOUT];
__device__ float  g_y0[2*(size_t)BATCH*2*DOUT];
__device__ float  g_T[2*(size_t)N1*HIDW];
__device__ float  g_pool2[2*(size_t)BATCH*HIDW];

// ------------------------------- sampling ----------------------------------
__global__ void k_sample1(const int* __restrict__ b1, const int* __restrict__ b2,
                          const int* __restrict__ adj) {
    int i = blockIdx.x * blockDim.x + threadIdx.x;
    if (i >= 2 * N1) return;
    int t = i / N1, r = i % N1;
    int n = r / NS_B, j = r % NS_B;
    int node = (t ? b2 : b1)[n];
    if (j == 0) g_b12[t * BATCH + n] = node;
    g_s1[t * N1 + r] = adj[(size_t)node * DEG + j];
}
__global__ void k_sample2(const int* __restrict__ adj) {
    int i = blockIdx.x * blockDim.x + threadIdx.x;
    if (i >= 2 * N2) return;
    int t = i / N2, r = i % N2;
    int n = r / NS_A, j = r % NS_A;
    int parent = g_s1[t * N1 + n];
    g_s2[t * N2 + r] = adj[(size_t)parent * DEG + j];
}

// -------- fused weight prep: transpose + fp16 convert all 4 weights ---------
__global__ void k_trc_all(const float* __restrict__ Wp0, const float* __restrict__ Wn0,
                          const float* __restrict__ Ws0, const float* __restrict__ Wp1) {
    __shared__ float t[32][33];
    int b = blockIdx.x;
    const float* W; __half* out; int K, N;
    if (b < 128)      { W = Wp0; out = g_Wp0t; K = 256; N = 512; }
    else if (b < 192) { b -= 128; W = Wn0; out = g_Wn0t; K = 512; N = 128; }
    else if (b < 224) { b -= 192; W = Ws0; out = g_Ws0t; K = 256; N = 128; }
    else              { b -= 224; W = Wp1; out = g_Wp1t; K = 256; N = 512; }
    int tilesN = N / 32;
    int n0 = (b % tilesN) * 32, k0 = (b / tilesN) * 32;
    for (int i = threadIdx.y; i < 32; i += 8)
        t[i][threadIdx.x] = W[(size_t)(k0 + i) * N + n0 + threadIdx.x];
    __syncthreads();
    for (int i = threadIdx.y; i < 32; i += 8)
        out[(size_t)(n0 + i) * K + k0 + threadIdx.x] =
            __float2half_rn(t[threadIdx.x][i]);
}

// ---------------- features fp32 -> fp16 (rn; bit-identical to mainloop cvt) -
__global__ void k_feat2h(const float* __restrict__ feat, int row0, int nrows) {
    size_t i = (size_t)blockIdx.x * blockDim.x + threadIdx.x;
    size_t total = (size_t)nrows * FEAT / 8;
    if (i >= total) return;
    const float4* src = (const float4*)(feat + (size_t)row0 * FEAT) + i * 2;
    float4 a = src[0], b = src[1];
    __half2 h[4] = { __floats2half2_rn(a.x, a.y), __floats2half2_rn(a.z, a.w),
                     __floats2half2_rn(b.x, b.y), __floats2half2_rn(b.z, b.w) };
    __half* dst = g_featH + (size_t)row0 * FEAT;
    *((uint4*)dst + i) = *(uint4*)h;
}

// ----------------------------- fp16 MMA GEMM --------------------------------
__device__ __forceinline__ void mma_f16(float c[4], uint32_t a0, uint32_t a1,
                                        uint32_t a2, uint32_t a3,
                                        uint32_t b0, uint32_t b1) {
    asm volatile(
        "mma.sync.aligned.m16n8k16.row.col.f32.f16.f16.f32 "
        "{%0,%1,%2,%3}, {%4,%5,%6,%7}, {%8,%9}, {%0,%1,%2,%3};"
        : "+f"(c[0]), "+f"(c[1]), "+f"(c[2]), "+f"(c[3])
        : "r"(a0), "r"(a1), "r"(a2), "r"(a3), "r"(b0), "r"(b1));
}
__device__ __forceinline__ void ldsm_x4(uint32_t& r0, uint32_t& r1,
                                        uint32_t& r2, uint32_t& r3,
                                        uint32_t addr) {
    asm volatile("ldmatrix.sync.aligned.m8n8.x4.shared.b16 {%0,%1,%2,%3}, [%4];"
                 : "=r"(r0), "=r"(r1), "=r"(r2), "=r"(r3) : "r"(addr));
}
__device__ __forceinline__ void cp16(uint32_t dst, const void* src, uint32_t sz) {
    asm volatile("cp.async.cg.shared.global [%0], [%1], 16, %2;"
                 :: "r"(dst), "l"(src), "r"(sz) : "memory");
}
#define CP_COMMIT() asm volatile("cp.async.commit_group;" ::: "memory")
#define CP_WAIT1()  asm volatile("cp.async.wait_group 1;" ::: "memory")
#define CP_WAIT0()  asm volatile("cp.async.wait_group 0;" ::: "memory")

// A: fp16 [*, K] K-contig (optionally gathered). Bt: fp16 [N][K] K-contig.
// BM=128, BN=128, BK=32; 256 thr = 8 warps (2m x 4n), warp tile 64x32.
// 3-stage cp.async pipeline; final tiles drain with wait_group 0.
template<bool OUTH, bool RELU>
__global__ __launch_bounds__(256, 2)
void k_gemm_f16(const __half* __restrict__ A, const int* __restrict__ gidx,
                int M, int K,
                const __half* __restrict__ Bt,
                const float* __restrict__ bias,
                void* __restrict__ Cv, int ldc)
{
    constexpr int BM = 128, BK = 32, STG = 3;
    constexpr int LDSH = BK + 8;                       // 40 halves (80B)/row
    constexpr uint32_t SROW = BM * LDSH * 2;           // stage stride bytes
    extern __shared__ __align__(16) __half sm[];

    const int tid  = threadIdx.x;
    const int lane = tid & 31;
    const int warp = tid >> 5;
    const int wm = warp >> 2, wn = warp & 3;
    const int m0g = blockIdx.x * BM;
    const int n0g = blockIdx.y * 128;

    const uint32_t as0 = (uint32_t)__cvta_generic_to_shared(sm);
    const uint32_t bs0 = as0 + STG * SROW;

    float acc[4][4][4];
#pragma unroll
    for (int i = 0; i < 4; i++)
#pragma unroll
        for (int j = 0; j < 4; j++)
#pragma unroll
            for (int r = 0; r < 4; r++) acc[i][j][r] = 0.f;

    auto load_stage = [&](int s, int kk) {
#pragma unroll
        for (int i = 0; i < 2; i++) {
            int f = tid + i * 256;
            int m = f >> 2, u = f & 3;
            int row = m0g + m;
            bool v = row < M;
            const __half* srcA = A;
            if (v) {
                int r = gidx ? gidx[row] : row;
                srcA = A + (size_t)r * K + kk + u * 8;
            }
            cp16(as0 + s * SROW + (m * LDSH + u * 8) * 2, srcA, v ? 16u : 0u);
            cp16(bs0 + s * SROW + (m * LDSH + u * 8) * 2,
                 Bt + (size_t)(n0g + m) * K + kk + u * 8, 16u);
        }
        CP_COMMIT();
    };

    const int m_base = wm * 64, n_base = wn * 32;
    const int rql = lane >> 2, cql = lane & 3;

    uint32_t aoff[4], boff[2];
#pragma unroll
    for (int mt = 0; mt < 4; mt++)
        aoff[mt] = ((m_base + mt * 16 + (lane & 15)) * LDSH + (lane >> 4) * 8) * 2;
#pragma unroll
    for (int p = 0; p < 2; p++) {
        int rowb = n_base + p * 16 + ((lane >> 4) & 1) * 8 + (lane & 7);
        boff[p] = (rowb * LDSH + ((lane >> 3) & 1) * 8) * 2;
    }

    const int ktiles = K / BK;
    load_stage(0, 0);
    load_stage(1, BK);

    for (int kt = 0; kt < ktiles; kt++) {
        // R6 BUG FIX: once no further groups are committed, wait_group 1 would
        // leave the newest group (this iteration's tile) pending. Drain fully.
        if (kt + 2 < ktiles) CP_WAIT1(); else CP_WAIT0();
        __syncthreads();
        if (kt + 2 < ktiles) load_stage((kt + 2) % STG, (kt + 2) * BK);

        const int s = kt % STG;
#pragma unroll
        for (int k0 = 0; k0 < BK; k0 += 16) {
            uint32_t af[4][4], bf[4][2];
            const uint32_t ab = as0 + s * SROW + k0 * 2;
            const uint32_t bb = bs0 + s * SROW + k0 * 2;
#pragma unroll
            for (int mt = 0; mt < 4; mt++)
                ldsm_x4(af[mt][0], af[mt][1], af[mt][2], af[mt][3], ab + aoff[mt]);
#pragma unroll
            for (int p = 0; p < 2; p++)
                ldsm_x4(bf[2 * p][0], bf[2 * p][1], bf[2 * p + 1][0],
                        bf[2 * p + 1][1], bb + boff[p]);
#pragma unroll
            for (int mt = 0; mt < 4; mt++)
#pragma unroll
                for (int nt = 0; nt < 4; nt++)
                    mma_f16(acc[mt][nt], af[mt][0], af[mt][1], af[mt][2],
                            af[mt][3], bf[nt][0], bf[nt][1]);
        }
        __syncthreads();
    }

    // epilogue
#pragma unroll
    for (int mt = 0; mt < 4; mt++) {
#pragma unroll
        for (int half = 0; half < 2; half++) {
            int row = m0g + m_base + mt * 16 + rql + half * 8;
            if (row >= M) continue;
#pragma unroll
            for (int nt = 0; nt < 4; nt++) {
                int col = n0g + n_base + nt * 8 + cql * 2;
                float2 v;
                v.x = acc[mt][nt][half * 2 + 0];
                v.y = acc[mt][nt][half * 2 + 1];
                if (bias) { v.x += bias[col]; v.y += bias[col + 1]; }
                if (RELU) { v.x = fmaxf(v.x, 0.f); v.y = fmaxf(v.y, 0.f); }
                if (OUTH) {
                    *(__half2*)((__half*)Cv + (size_t)row * ldc + col) =
                        __floats2half2_rn(v.x, v.y);
                } else {
                    *(float2*)((float*)Cv + (size_t)row * ldc + col) = v;
                }
            }
        }
    }
}

// --------------------- segmented gather-max (fp16) --------------------------
template<int NB>
__global__ void k_poolmax_h(const __half* __restrict__ src,
                            const int* __restrict__ idx,
                            __half* __restrict__ dst)
{
    int g = blockIdx.x;
    __shared__ int sidx[NB];
    if (threadIdx.x < NB)
        sidx[threadIdx.x] = idx[g * NB + threadIdx.x];
    __syncthreads();
    int c = threadIdx.x * 8;     // 64 threads x 8 halves = 512 cols
    __half2 m0 = __float2half2_rn(0.f), m1 = m0, m2 = m0, m3 = m0;
#pragma unroll
    for (int j = 0; j < NB; j++) {
        uint4 v = *(const uint4*)(src + (size_t)sidx[j] * HIDW + c);
        const __half2* h = (const __half2*)&v;
        m0 = __hmax2(m0, h[0]);
        m1 = __hmax2(m1, h[1]);
        m2 = __hmax2(m2, h[2]);
        m3 = __hmax2(m3, h[3]);
    }
    __half2 r[4] = { m0, m1, m2, m3 };
    *(uint4*)(dst + (size_t)g * HIDW + c) = *(uint4*)r;
}

// --------------------- segmented max (fp32, consecutive) --------------------
template<int NB>
__global__ void k_poolmax_f(const float* __restrict__ src, float* __restrict__ dst)
{
    int g = blockIdx.x;
    int c = threadIdx.x * 4;
    float4 m = make_float4(-1e30f, -1e30f, -1e30f, -1e30f);
#pragma unroll
    for (int j = 0; j < NB; j++) {
        const float4 v = *(const float4*)(src + (size_t)(g * NB + j) * HIDW + c);
        m.x = fmaxf(m.x, v.x);
        m.y = fmaxf(m.y, v.y);
        m.z = fmaxf(m.z, v.z);
        m.w = fmaxf(m.w, v.w);
    }
    *(float4*)(dst + (size_t)g * HIDW + c) = m;
}

// -------------------- layer-1 combine + L2 normalize ------------------------
__global__ void k_final(const float* __restrict__ y0, const float* __restrict__ p2,
                        const float* __restrict__ Ws1, const float* __restrict__ Wn1,
                        float* __restrict__ out)
{
    int n = blockIdx.x;
    __shared__ float ss[256];
    __shared__ float sp[512];
    __shared__ float red[256];
    int tid = threadIdx.x;
    ss[tid] = y0[(size_t)n * 256 + tid];
    sp[tid] = p2[(size_t)n * 512 + tid];
    sp[256 + tid] = p2[(size_t)n * 512 + 256 + tid];
    __syncthreads();

    float acc = 0.f;
    if (tid < 128) {
#pragma unroll 8
        for (int k = 0; k < 256; k++) acc += ss[k] * Ws1[k * 128 + tid];
    } else {
        int c = tid - 128;
#pragma unroll 8
        for (int k = 0; k < 512; k++) acc += sp[k] * Wn1[k * 128 + c];
    }
    red[tid] = acc * acc;
    __syncthreads();
    for (int s = 128; s > 0; s >>= 1) {
        if (tid < s) red[tid] += red[tid + s];
        __syncthreads();
    }
    float inv = 1.f / fmaxf(sqrtf(red[0]), 1e-12f);
    out[(size_t)n * 256 + tid] = acc * inv;
}

// ------------------------------- launcher -----------------------------------
#define GEMM_SMEM (3 * 2 * 128 * 40 * 2)   // 61440 bytes

extern "C" void kernel_launch(void* const* d_in, const int* in_sizes, int n_in,
                              void* d_out, int out_size)
{
    (void)in_sizes; (void)n_in; (void)out_size;
    const int*   b1   = (const int*)d_in[0];
    const int*   b2   = (const int*)d_in[1];
    const float* feat = (const float*)d_in[2];
    const int*   adj  = (const int*)d_in[3];
    const float* Wp0  = (const float*)d_in[4];
    const float* bp0  = (const float*)d_in[5];
    const float* Wn0  = (const float*)d_in[6];
    const float* Ws0  = (const float*)d_in[7];
    const float* Wp1  = (const float*)d_in[8];
    const float* bp1  = (const float*)d_in[9];
    const float* Wn1  = (const float*)d_in[10];
    const float* Ws1  = (const float*)d_in[11];
    float* out = (float*)d_out;

    int *s1, *s2, *b12;
    __half *featH, *H, *pool1, *pool0, *y1, *Wp0t, *Wn0t, *Ws0t, *Wp1t;
    float *y0, *T, *pool2;
    cudaGetSymbolAddress((void**)&s1,    g_s1);
    cudaGetSymbolAddress((void**)&s2,    g_s2);
    cudaGetSymbolAddress((void**)&b12,   g_b12);
    cudaGetSymbolAddress((void**)&featH, g_featH);
    cudaGetSymbolAddress((void**)&H,     g_H);
    cudaGetSymbolAddress((void**)&pool1, g_pool1);
    cudaGetSymbolAddress((void**)&pool0, g_pool0);
    cudaGetSymbolAddress((void**)&y1,    g_y1);
    cudaGetSymbolAddress((void**)&y0,    g_y0);
    cudaGetSymbolAddress((void**)&T,     g_T);
    cudaGetSymbolAddress((void**)&pool2, g_pool2);
    cudaGetSymbolAddress((void**)&Wp0t,  g_Wp0t);
    cudaGetSymbolAddress((void**)&Wn0t,  g_Wn0t);
    cudaGetSymbolAddress((void**)&Ws0t,  g_Ws0t);
    cudaGetSymbolAddress((void**)&Wp1t,  g_Wp1t);

    cudaFuncSetAttribute(k_gemm_f16<true, true>,
                         cudaFuncAttributeMaxDynamicSharedMemorySize, GEMM_SMEM);
    cudaFuncSetAttribute(k_gemm_f16<false, true>,
                         cudaFuncAttributeMaxDynamicSharedMemorySize, GEMM_SMEM);

    // launches 0-4 (so ncu -s 5 profiles the H GEMM)
    k_sample1<<<(2 * N1 + 255) / 256, 256>>>(b1, b2, adj);
    k_sample2<<<(2 * N2 + 255) / 256, 256>>>(adj);
    k_trc_all<<<352, dim3(32, 8)>>>(Wp0, Wn0, Ws0, Wp1);
    k_feat2h<<<6250, 256>>>(feat, 0, 50000);
    k_feat2h<<<6250, 256>>>(feat, 50000, 50000);

    // launch 5: H_all = relu(featH @ W_pool0 + b)  [100000, 512] fp16 out
    k_gemm_f16<true, true><<<dim3((NN + 127) / 128, HIDW / 128), 256, GEMM_SMEM>>>(
        featH, nullptr, NN, FEAT, Wp0t, bp0, H, HIDW);

    // pools over H (fp16, both batches at once)
    k_poolmax_h<NS_A><<<2 * N1, 64>>>(H, s2, pool1);
    k_poolmax_h<NS_B><<<2 * BATCH, 64>>>(H, s1, pool0);

    // layer-0 combine (relu distributes over concat)
    k_gemm_f16<true, true><<<dim3(2 * N1 / 128, 1), 256, GEMM_SMEM>>>(
        featH, s1, 2 * N1, FEAT, Ws0t, nullptr, y1, 256);
    k_gemm_f16<true, true><<<dim3(2 * N1 / 128, 1), 256, GEMM_SMEM>>>(
        pool1, nullptr, 2 * N1, HIDW, Wn0t, nullptr, y1 + 128, 256);
    k_gemm_f16<false, true><<<dim3(2 * BATCH / 128, 1), 256, GEMM_SMEM>>>(
        featH, b12, 2 * BATCH, FEAT, Ws0t, nullptr, y0, 256);
    k_gemm_f16<false, true><<<dim3(2 * BATCH / 128, 1), 256, GEMM_SMEM>>>(
        pool0, nullptr, 2 * BATCH, HIDW, Wn0t, nullptr, y0 + 128, 256);

    // layer-1 pool MLP + consecutive segmax (fp32)
    k_gemm_f16<false, true><<<dim3(2 * N1 / 128, HIDW / 128), 256, GEMM_SMEM>>>(
        y1, nullptr, 2 * N1, 2 * DOUT, Wp1t, bp1, T, HIDW);
    k_poolmax_f<NS_B><<<2 * BATCH, 128>>>(T, pool2);

    // final combine + L2 normalize (exact fp32)
    k_final<<<2 * BATCH, 256>>>(y0, pool2, Ws1, Wn1, out);
}

// round 12
// speedup vs baseline: 4.5631x; 1.0346x over previous
#include <cuda_runtime.h>
#include <cuda_fp16.h>
#include <cstdint>

// ---------------------------------------------------------------------------
// SampleAndAggregate (GraphSAGE, 2-layer maxpool)
// Round 8: B-resident GEMM (weights loaded to SMEM once per CTA), 4-stage
//          A-only cp.async pipeline, one barrier per k-tile. All GEMMs on
//          this path. Merged feature conversion.
// ---------------------------------------------------------------------------

#define BATCH 512
#define FEAT  256
#define HIDW  512
#define DOUT  128
#define DEG   128
#define NN    100000
#define NS_A  25
#define NS_B  10
#define N1    (BATCH*NS_B)     // 5120
#define N2    (N1*NS_A)        // 128000

// ------------------------- scratch (device globals) ------------------------
__device__ int    g_s1[2*N1];
__device__ int    g_s2[2*N2];
__device__ int    g_b12[2*BATCH];
__device__ __half g_featH[(size_t)NN*FEAT];
__device__ __half g_Wp0t[HIDW*FEAT];   // [512][256]
__device__ __half g_Wn0t[DOUT*HIDW];   // [128][512]
__device__ __half g_Ws0t[DOUT*FEAT];   // [128][256]
__device__ __half g_Wp1t[HIDW*2*DOUT]; // [512][256]
__device__ __half g_H[(size_t)NN*HIDW];
__device__ __half g_pool1[2*(size_t)N1*HIDW];
__device__ __half g_pool0[2*(size_t)BATCH*HIDW];
__device__ __half g_y1[2*(size_t)N1*2*DOUT];
__device__ float  g_y0[2*(size_t)BATCH*2*DOUT];
__device__ float  g_T[2*(size_t)N1*HIDW];
__device__ float  g_pool2[2*(size_t)BATCH*HIDW];

// ------------------------------- sampling ----------------------------------
__global__ void k_sample1(const int* __restrict__ b1, const int* __restrict__ b2,
                          const int* __restrict__ adj) {
    int i = blockIdx.x * blockDim.x + threadIdx.x;
    if (i >= 2 * N1) return;
    int t = i / N1, r = i % N1;
    int n = r / NS_B, j = r % NS_B;
    int node = (t ? b2 : b1)[n];
    if (j == 0) g_b12[t * BATCH + n] = node;
    g_s1[t * N1 + r] = adj[(size_t)node * DEG + j];
}
__global__ void k_sample2(const int* __restrict__ adj) {
    int i = blockIdx.x * blockDim.x + threadIdx.x;
    if (i >= 2 * N2) return;
    int t = i / N2, r = i % N2;
    int n = r / NS_A, j = r % NS_A;
    int parent = g_s1[t * N1 + n];
    g_s2[t * N2 + r] = adj[(size_t)parent * DEG + j];
}

// -------- fused weight prep: transpose + fp16 convert all 4 weights ---------
__global__ void k_trc_all(const float* __restrict__ Wp0, const float* __restrict__ Wn0,
                          const float* __restrict__ Ws0, const float* __restrict__ Wp1) {
    __shared__ float t[32][33];
    int b = blockIdx.x;
    const float* W; __half* out; int K, N;
    if (b < 128)      { W = Wp0; out = g_Wp0t; K = 256; N = 512; }
    else if (b < 192) { b -= 128; W = Wn0; out = g_Wn0t; K = 512; N = 128; }
    else if (b < 224) { b -= 192; W = Ws0; out = g_Ws0t; K = 256; N = 128; }
    else              { b -= 224; W = Wp1; out = g_Wp1t; K = 256; N = 512; }
    int tilesN = N / 32;
    int n0 = (b % tilesN) * 32, k0 = (b / tilesN) * 32;
    for (int i = threadIdx.y; i < 32; i += 8)
        t[i][threadIdx.x] = W[(size_t)(k0 + i) * N + n0 + threadIdx.x];
    __syncthreads();
    for (int i = threadIdx.y; i < 32; i += 8)
        out[(size_t)(n0 + i) * K + k0 + threadIdx.x] =
            __float2half_rn(t[threadIdx.x][i]);
}

// ---------------- features fp32 -> fp16 (rn; bit-identical) -----------------
__global__ void k_feat2h(const float* __restrict__ feat) {
    size_t i = (size_t)blockIdx.x * blockDim.x + threadIdx.x;
    const float4* src = (const float4*)feat + i * 2;
    float4 a = src[0], b = src[1];
    __half2 h[4] = { __floats2half2_rn(a.x, a.y), __floats2half2_rn(a.z, a.w),
                     __floats2half2_rn(b.x, b.y), __floats2half2_rn(b.z, b.w) };
    *((uint4*)g_featH + i) = *(uint4*)h;
}

// ----------------------------- fp16 MMA GEMM --------------------------------
__device__ __forceinline__ void mma_f16(float c[4], uint32_t a0, uint32_t a1,
                                        uint32_t a2, uint32_t a3,
                                        uint32_t b0, uint32_t b1) {
    asm volatile(
        "mma.sync.aligned.m16n8k16.row.col.f32.f16.f16.f32 "
        "{%0,%1,%2,%3}, {%4,%5,%6,%7}, {%8,%9}, {%0,%1,%2,%3};"
        : "+f"(c[0]), "+f"(c[1]), "+f"(c[2]), "+f"(c[3])
        : "r"(a0), "r"(a1), "r"(a2), "r"(a3), "r"(b0), "r"(b1));
}
__device__ __forceinline__ void ldsm_x4(uint32_t& r0, uint32_t& r1,
                                        uint32_t& r2, uint32_t& r3,
                                        uint32_t addr) {
    asm volatile("ldmatrix.sync.aligned.m8n8.x4.shared.b16 {%0,%1,%2,%3}, [%4];"
                 : "=r"(r0), "=r"(r1), "=r"(r2), "=r"(r3) : "r"(addr));
}
__device__ __forceinline__ void cp16(uint32_t dst, const void* src, uint32_t sz) {
    asm volatile("cp.async.cg.shared.global [%0], [%1], 16, %2;"
                 :: "r"(dst), "l"(src), "r"(sz) : "memory");
}
#define CP_COMMIT() asm volatile("cp.async.commit_group;" ::: "memory")
#define CP_WAIT(n)  asm volatile("cp.async.wait_group %0;" :: "n"(n) : "memory")

// ---------------------------------------------------------------------------
// B-resident GEMM.  C[row, n0g:+128] = act(A[gidx?[row]] @ Bt^T + bias)
// A: fp16 [*, KT] K-contig.  Bt: fp16 [N][KT] K-contig; this CTA's 128-row
// slice of Bt is loaded to SMEM once.  A streams via 4-stage cp.async.
// BM=128, BN=128, BK=32; 256 threads = 8 warps (2m x 4n), warp tile 64x32.
// ---------------------------------------------------------------------------
template<int KT, bool OUTH, bool RELU>
__global__ __launch_bounds__(256, (KT == 256 ? 2 : 1))
void k_gemm_bres(const __half* __restrict__ A, const int* __restrict__ gidx,
                 int M,
                 const __half* __restrict__ Bt,
                 const float* __restrict__ bias,
                 void* __restrict__ Cv, int ldc)
{
    constexpr int BM = 128, BK = 32, STG = 4;
    constexpr int LDA = BK + 8;            // 40 halves (80B) per A row
    constexpr int LDB = KT + 8;            // (KT+8) halves per B row
    constexpr int ktiles = KT / BK;
    constexpr uint32_t ABUF = BM * LDA * 2;        // A stage bytes
    extern __shared__ __align__(16) __half sm[];

    const int tid  = threadIdx.x;
    const int lane = tid & 31;
    const int warp = tid >> 5;
    const int wm = warp >> 2, wn = warp & 3;
    const int m0g = blockIdx.x * BM;
    const int n0g = blockIdx.y * 128;

    const uint32_t b_base = (uint32_t)__cvta_generic_to_shared(sm);
    const uint32_t a_base = b_base + 128 * LDB * 2;

    // ---- load this CTA's B slice (128 x KT fp16) once ----
    constexpr int BCH = 128 * (KT / 8) / 256;      // 16B chunks per thread
#pragma unroll
    for (int i = 0; i < BCH; i++) {
        int f = tid + i * 256;
        int row = f / (KT / 8), u = f % (KT / 8);
        cp16(b_base + (row * LDB + u * 8) * 2,
             Bt + (size_t)(n0g + row) * KT + u * 8, 16u);
    }
    CP_COMMIT();

    float acc[4][4][4];
#pragma unroll
    for (int i = 0; i < 4; i++)
#pragma unroll
        for (int j = 0; j < 4; j++)
#pragma unroll
            for (int r = 0; r < 4; r++) acc[i][j][r] = 0.f;

    // A stage loader: 2 x 16B per thread
    auto load_A = [&](int s, int kk) {
#pragma unroll
        for (int i = 0; i < 2; i++) {
            int f = tid + i * 256;
            int m = f >> 2, u = f & 3;
            int row = m0g + m;
            bool v = row < M;
            const __half* src = A;
            if (v) {
                int r = gidx ? gidx[row] : row;
                src = A + (size_t)r * KT + kk + u * 8;
            }
            cp16(a_base + s * ABUF + (m * LDA + u * 8) * 2, src, v ? 16u : 0u);
        }
        CP_COMMIT();
    };

    const int m_base = wm * 64, n_base = wn * 32;
    const int rql = lane >> 2, cql = lane & 3;

    uint32_t aoff[4], boff[2];
#pragma unroll
    for (int mt = 0; mt < 4; mt++)
        aoff[mt] = ((m_base + mt * 16 + (lane & 15)) * LDA + (lane >> 4) * 8) * 2;
#pragma unroll
    for (int p = 0; p < 2; p++) {
        int rowb = n_base + p * 16 + ((lane >> 4) & 1) * 8 + (lane & 7);
        boff[p] = (rowb * LDB + ((lane >> 3) & 1) * 8) * 2;
    }

    load_A(0, 0);
    load_A(1, BK);
    load_A(2, 2 * BK);

    for (int kt = 0; kt < ktiles; kt++) {
        // ensure stage kt (and, first time, the B slice) has landed
        const int rem = ktiles - 1 - kt;
        if (rem >= 2) CP_WAIT(2);
        else if (rem == 1) CP_WAIT(1);
        else CP_WAIT(0);
        __syncthreads();   // single barrier/tile: also makes stage (kt-1)%4 safe to refill
        if (kt + 3 < ktiles) load_A((kt + 3) % STG, (kt + 3) * BK);

        const int s = kt % STG;
#pragma unroll
        for (int k0 = 0; k0 < BK; k0 += 16) {
            uint32_t af[4][4], bf[4][2];
            const uint32_t ab = a_base + s * ABUF + k0 * 2;
            const uint32_t bb = b_base + (kt * BK + k0) * 2;
#pragma unroll
            for (int mt = 0; mt < 4; mt++)
                ldsm_x4(af[mt][0], af[mt][1], af[mt][2], af[mt][3], ab + aoff[mt]);
#pragma unroll
            for (int p = 0; p < 2; p++)
                ldsm_x4(bf[2 * p][0], bf[2 * p][1], bf[2 * p + 1][0],
                        bf[2 * p + 1][1], bb + boff[p]);
#pragma unroll
            for (int mt = 0; mt < 4; mt++)
#pragma unroll
                for (int nt = 0; nt < 4; nt++)
                    mma_f16(acc[mt][nt], af[mt][0], af[mt][1], af[mt][2],
                            af[mt][3], bf[nt][0], bf[nt][1]);
        }
    }

    // epilogue
#pragma unroll
    for (int mt = 0; mt < 4; mt++) {
#pragma unroll
        for (int half = 0; half < 2; half++) {
            int row = m0g + m_base + mt * 16 + rql + half * 8;
            if (row >= M) continue;
#pragma unroll
            for (int nt = 0; nt < 4; nt++) {
                int col = n0g + n_base + nt * 8 + cql * 2;
                float2 v;
                v.x = acc[mt][nt][half * 2 + 0];
                v.y = acc[mt][nt][half * 2 + 1];
                if (bias) { v.x += bias[col]; v.y += bias[col + 1]; }
                if (RELU) { v.x = fmaxf(v.x, 0.f); v.y = fmaxf(v.y, 0.f); }
                if (OUTH) {
                    *(__half2*)((__half*)Cv + (size_t)row * ldc + col) =
                        __floats2half2_rn(v.x, v.y);
                } else {
                    *(float2*)((float*)Cv + (size_t)row * ldc + col) = v;
                }
            }
        }
    }
}

// --------------------- segmented gather-max (fp16) --------------------------
template<int NB>
__global__ void k_poolmax_h(const __half* __restrict__ src,
                            const int* __restrict__ idx,
                            __half* __restrict__ dst)
{
    int g = blockIdx.x;
    __shared__ int sidx[NB];
    if (threadIdx.x < NB)
        sidx[threadIdx.x] = idx[g * NB + threadIdx.x];
    __syncthreads();
    int c = threadIdx.x * 8;
    __half2 m0 = __float2half2_rn(0.f), m1 = m0, m2 = m0, m3 = m0;
#pragma unroll
    for (int j = 0; j < NB; j++) {
        uint4 v = *(const uint4*)(src + (size_t)sidx[j] * HIDW + c);
        const __half2* h = (const __half2*)&v;
        m0 = __hmax2(m0, h[0]);
        m1 = __hmax2(m1, h[1]);
        m2 = __hmax2(m2, h[2]);
        m3 = __hmax2(m3, h[3]);
    }
    __half2 r[4] = { m0, m1, m2, m3 };
    *(uint4*)(dst + (size_t)g * HIDW + c) = *(uint4*)r;
}

// --------------------- segmented max (fp32, consecutive) --------------------
template<int NB>
__global__ void k_poolmax_f(const float* __restrict__ src, float* __restrict__ dst)
{
    int g = blockIdx.x;
    int c = threadIdx.x * 4;
    float4 m = make_float4(-1e30f, -1e30f, -1e30f, -1e30f);
#pragma unroll
    for (int j = 0; j < NB; j++) {
        const float4 v = *(const float4*)(src + (size_t)(g * NB + j) * HIDW + c);
        m.x = fmaxf(m.x, v.x);
        m.y = fmaxf(m.y, v.y);
        m.z = fmaxf(m.z, v.z);
        m.w = fmaxf(m.w, v.w);
    }
    *(float4*)(dst + (size_t)g * HIDW + c) = m;
}

// -------------------- layer-1 combine + L2 normalize ------------------------
__global__ void k_final(const float* __restrict__ y0, const float* __restrict__ p2,
                        const float* __restrict__ Ws1, const float* __restrict__ Wn1,
                        float* __restrict__ out)
{
    int n = blockIdx.x;
    __shared__ float ss[256];
    __shared__ float sp[512];
    __shared__ float red[256];
    int tid = threadIdx.x;
    ss[tid] = y0[(size_t)n * 256 + tid];
    sp[tid] = p2[(size_t)n * 512 + tid];
    sp[256 + tid] = p2[(size_t)n * 512 + 256 + tid];
    __syncthreads();

    float acc = 0.f;
    if (tid < 128) {
#pragma unroll 8
        for (int k = 0; k < 256; k++) acc += ss[k] * Ws1[k * 128 + tid];
    } else {
        int c = tid - 128;
#pragma unroll 8
        for (int k = 0; k < 512; k++) acc += sp[k] * Wn1[k * 128 + c];
    }
    red[tid] = acc * acc;
    __syncthreads();
    for (int s = 128; s > 0; s >>= 1) {
        if (tid < s) red[tid] += red[tid + s];
        __syncthreads();
    }
    float inv = 1.f / fmaxf(sqrtf(red[0]), 1e-12f);
    out[(size_t)n * 256 + tid] = acc * inv;
}

// ------------------------------- launcher -----------------------------------
#define SMEM_K256 ((128 * (256 + 8) + 4 * 128 * 40) * 2)   // 108544
#define SMEM_K512 ((128 * (512 + 8) + 4 * 128 * 40) * 2)   // 174080

extern "C" void kernel_launch(void* const* d_in, const int* in_sizes, int n_in,
                              void* d_out, int out_size)
{
    (void)in_sizes; (void)n_in; (void)out_size;
    const int*   b1   = (const int*)d_in[0];
    const int*   b2   = (const int*)d_in[1];
    const float* feat = (const float*)d_in[2];
    const int*   adj  = (const int*)d_in[3];
    const float* Wp0  = (const float*)d_in[4];
    const float* bp0  = (const float*)d_in[5];
    const float* Wn0  = (const float*)d_in[6];
    const float* Ws0  = (const float*)d_in[7];
    const float* Wp1  = (const float*)d_in[8];
    const float* bp1  = (const float*)d_in[9];
    const float* Wn1  = (const float*)d_in[10];
    const float* Ws1  = (const float*)d_in[11];
    float* out = (float*)d_out;

    int *s1, *s2, *b12;
    __half *featH, *H, *pool1, *pool0, *y1, *Wp0t, *Wn0t, *Ws0t, *Wp1t;
    float *y0, *T, *pool2;
    cudaGetSymbolAddress((void**)&s1,    g_s1);
    cudaGetSymbolAddress((void**)&s2,    g_s2);
    cudaGetSymbolAddress((void**)&b12,   g_b12);
    cudaGetSymbolAddress((void**)&featH, g_featH);
    cudaGetSymbolAddress((void**)&H,     g_H);
    cudaGetSymbolAddress((void**)&pool1, g_pool1);
    cudaGetSymbolAddress((void**)&pool0, g_pool0);
    cudaGetSymbolAddress((void**)&y1,    g_y1);
    cudaGetSymbolAddress((void**)&y0,    g_y0);
    cudaGetSymbolAddress((void**)&T,     g_T);
    cudaGetSymbolAddress((void**)&pool2, g_pool2);
    cudaGetSymbolAddress((void**)&Wp0t,  g_Wp0t);
    cudaGetSymbolAddress((void**)&Wn0t,  g_Wn0t);
    cudaGetSymbolAddress((void**)&Ws0t,  g_Ws0t);
    cudaGetSymbolAddress((void**)&Wp1t,  g_Wp1t);

    cudaFuncSetAttribute(k_gemm_bres<256, true,  true>,
                         cudaFuncAttributeMaxDynamicSharedMemorySize, SMEM_K256);
    cudaFuncSetAttribute(k_gemm_bres<256, false, true>,
                         cudaFuncAttributeMaxDynamicSharedMemorySize, SMEM_K256);
    cudaFuncSetAttribute(k_gemm_bres<512, true,  true>,
                         cudaFuncAttributeMaxDynamicSharedMemorySize, SMEM_K512);
    cudaFuncSetAttribute(k_gemm_bres<512, false, true>,
                         cudaFuncAttributeMaxDynamicSharedMemorySize, SMEM_K512);

    // prep
    k_sample1<<<(2 * N1 + 255) / 256, 256>>>(b1, b2, adj);
    k_sample2<<<(2 * N2 + 255) / 256, 256>>>(adj);
    k_trc_all<<<352, dim3(32, 8)>>>(Wp0, Wn0, Ws0, Wp1);
    k_feat2h<<<12500, 256>>>(feat);

    // H_all = relu(featH @ W_pool0 + b)  [100000, 512] fp16 out
    k_gemm_bres<256, true, true><<<dim3((NN + 127) / 128, HIDW / 128), 256, SMEM_K256>>>(
        featH, nullptr, NN, Wp0t, bp0, H, HIDW);

    // pools over H (fp16, both batches at once)
    k_poolmax_h<NS_A><<<2 * N1, 64>>>(H, s2, pool1);
    k_poolmax_h<NS_B><<<2 * BATCH, 64>>>(H, s1, pool0);

    // layer-0 combine (relu distributes over concat)
    k_gemm_bres<256, true, true><<<dim3(2 * N1 / 128, 1), 256, SMEM_K256>>>(
        featH, s1, 2 * N1, Ws0t, nullptr, y1, 256);
    k_gemm_bres<512, true, true><<<dim3(2 * N1 / 128, 1), 256, SMEM_K512>>>(
        pool1, nullptr, 2 * N1, Wn0t, nullptr, y1 + 128, 256);
    k_gemm_bres<256, false, true><<<dim3(2 * BATCH / 128, 1), 256, SMEM_K256>>>(
        featH, b12, 2 * BATCH, Ws0t, nullptr, y0, 256);
    k_gemm_bres<512, false, true><<<dim3(2 * BATCH / 128, 1), 256, SMEM_K512>>>(
        pool0, nullptr, 2 * BATCH, Wn0t, nullptr, y0 + 128, 256);

    // layer-1 pool MLP + consecutive segmax (fp32)
    k_gemm_bres<256, false, true><<<dim3(2 * N1 / 128, HIDW / 128), 256, SMEM_K256>>>(
        y1, nullptr, 2 * N1, Wp1t, bp1, T, HIDW);
    k_poolmax_f<NS_B><<<2 * BATCH, 128>>>(T, pool2);

    // final combine + L2 normalize (exact fp32)
    k_final<<<2 * BATCH, 256>>>(y0, pool2, Ws1, Wn1, out);
}

// round 14
// speedup vs baseline: 5.0925x; 1.1160x over previous
#include <cuda_runtime.h>
#include <cuda_fp16.h>
#include <cstdint>

// ---------------------------------------------------------------------------
// SampleAndAggregate (GraphSAGE, 2-layer maxpool)
// Round 14 (= R13 resubmit after infra failure): launch packing — merged
// layer-0 GEMMs (one 176-CTA launch), merged pools, merged prep; H GEMM at
// launch index 3 so ncu profiles it.
// ---------------------------------------------------------------------------

#define BATCH 512
#define FEAT  256
#define HIDW  512
#define DOUT  128
#define DEG   128
#define NN    100000
#define NS_A  25
#define NS_B  10
#define N1    (BATCH*NS_B)     // 5120
#define N2    (N1*NS_A)        // 128000

// ------------------------- scratch (device globals) ------------------------
__device__ int    g_s1[2*N1];
__device__ int    g_s2[2*N2];
__device__ int    g_b12[2*BATCH];
__device__ __half g_featH[(size_t)NN*FEAT];
__device__ __half g_Wp0t[HIDW*FEAT];   // [512][256]
__device__ __half g_Wn0t[DOUT*HIDW];   // [128][512]
__device__ __half g_Ws0t[DOUT*FEAT];   // [128][256]
__device__ __half g_Wp1t[HIDW*2*DOUT]; // [512][256]
__device__ __half g_H[(size_t)NN*HIDW];
__device__ __half g_pool1[2*(size_t)N1*HIDW];
__device__ __half g_pool0[2*(size_t)BATCH*HIDW];
__device__ __half g_y1[2*(size_t)N1*2*DOUT];
__device__ float  g_y0[2*(size_t)BATCH*2*DOUT];
__device__ float  g_T[2*(size_t)N1*HIDW];
__device__ float  g_pool2[2*(size_t)BATCH*HIDW];

// ------------------------------- sampling ----------------------------------
__global__ void k_sample1(const int* __restrict__ b1, const int* __restrict__ b2,
                          const int* __restrict__ adj) {
    int i = blockIdx.x * blockDim.x + threadIdx.x;
    if (i >= 2 * N1) return;
    int t = i / N1, r = i % N1;
    int n = r / NS_B, j = r % NS_B;
    int node = (t ? b2 : b1)[n];
    if (j == 0) g_b12[t * BATCH + n] = node;
    g_s1[t * N1 + r] = adj[(size_t)node * DEG + j];
}
__global__ void k_sample2(const int* __restrict__ adj) {
    int i = blockIdx.x * blockDim.x + threadIdx.x;
    if (i >= 2 * N2) return;
    int t = i / N2, r = i % N2;
    int n = r / NS_A, j = r % NS_A;
    int parent = g_s1[t * N1 + n];
    g_s2[t * N2 + r] = adj[(size_t)parent * DEG + j];
}

// ----- merged prep: weight transpose+cvt (blocks 0..351) + feat cvt rest ----
__global__ void k_prep(const float* __restrict__ Wp0, const float* __restrict__ Wn0,
                       const float* __restrict__ Ws0, const float* __restrict__ Wp1,
                       const float* __restrict__ feat) {
    int b = blockIdx.x;
    int tid = threadIdx.x;
    if (b < 352) {
        __shared__ float t[32][33];
        int tx = tid & 31, ty = tid >> 5;
        const float* W; __half* out; int K, N;
        if (b < 128)      { W = Wp0; out = g_Wp0t; K = 256; N = 512; }
        else if (b < 192) { b -= 128; W = Wn0; out = g_Wn0t; K = 512; N = 128; }
        else if (b < 224) { b -= 192; W = Ws0; out = g_Ws0t; K = 256; N = 128; }
        else              { b -= 224; W = Wp1; out = g_Wp1t; K = 256; N = 512; }
        int tilesN = N / 32;
        int n0 = (b % tilesN) * 32, k0 = (b / tilesN) * 32;
        for (int i = ty; i < 32; i += 8)
            t[i][tx] = W[(size_t)(k0 + i) * N + n0 + tx];
        __syncthreads();
        for (int i = ty; i < 32; i += 8)
            out[(size_t)(n0 + i) * K + k0 + tx] = __float2half_rn(t[tx][i]);
    } else {
        size_t i = (size_t)(b - 352) * 256 + tid;
        const float4* src = (const float4*)feat + i * 2;
        float4 a = src[0], c = src[1];
        __half2 h[4] = { __floats2half2_rn(a.x, a.y), __floats2half2_rn(a.z, a.w),
                         __floats2half2_rn(c.x, c.y), __floats2half2_rn(c.z, c.w) };
        *((uint4*)g_featH + i) = *(uint4*)h;
    }
}

// ----------------------------- fp16 MMA helpers -----------------------------
__device__ __forceinline__ void mma_f16(float c[4], uint32_t a0, uint32_t a1,
                                        uint32_t a2, uint32_t a3,
                                        uint32_t b0, uint32_t b1) {
    asm volatile(
        "mma.sync.aligned.m16n8k16.row.col.f32.f16.f16.f32 "
        "{%0,%1,%2,%3}, {%4,%5,%6,%7}, {%8,%9}, {%0,%1,%2,%3};"
        : "+f"(c[0]), "+f"(c[1]), "+f"(c[2]), "+f"(c[3])
        : "r"(a0), "r"(a1), "r"(a2), "r"(a3), "r"(b0), "r"(b1));
}
__device__ __forceinline__ void ldsm_x4(uint32_t& r0, uint32_t& r1,
                                        uint32_t& r2, uint32_t& r3,
                                        uint32_t addr) {
    asm volatile("ldmatrix.sync.aligned.m8n8.x4.shared.b16 {%0,%1,%2,%3}, [%4];"
                 : "=r"(r0), "=r"(r1), "=r"(r2), "=r"(r3) : "r"(addr));
}
__device__ __forceinline__ void cp16(uint32_t dst, const void* src, uint32_t sz) {
    asm volatile("cp.async.cg.shared.global [%0], [%1], 16, %2;"
                 :: "r"(dst), "l"(src), "r"(sz) : "memory");
}
#define CP_COMMIT() asm volatile("cp.async.commit_group;" ::: "memory")
#define CP_WAIT(n)  asm volatile("cp.async.wait_group %0;" :: "n"(n) : "memory")

// ---------------------------------------------------------------------------
// Templated B-resident GEMM (used for H and T GEMMs, KT=256, occupancy 2).
// ---------------------------------------------------------------------------
template<int KT, bool OUTH, bool RELU>
__global__ __launch_bounds__(256, (KT == 256 ? 2 : 1))
void k_gemm_bres(const __half* __restrict__ A, const int* __restrict__ gidx,
                 int M,
                 const __half* __restrict__ Bt,
                 const float* __restrict__ bias,
                 void* __restrict__ Cv, int ldc)
{
    constexpr int BM = 128, BK = 32, STG = 4;
    constexpr int LDA = BK + 8;
    constexpr int LDB = KT + 8;
    constexpr int ktiles = KT / BK;
    constexpr uint32_t ABUF = BM * LDA * 2;
    extern __shared__ __align__(16) __half sm[];

    const int tid  = threadIdx.x;
    const int lane = tid & 31;
    const int warp = tid >> 5;
    const int wm = warp >> 2, wn = warp & 3;
    const int m0g = blockIdx.x * BM;
    const int n0g = blockIdx.y * 128;

    const uint32_t b_base = (uint32_t)__cvta_generic_to_shared(sm);
    const uint32_t a_base = b_base + 128 * LDB * 2;

    constexpr int BCH = 128 * (KT / 8) / 256;
#pragma unroll
    for (int i = 0; i < BCH; i++) {
        int f = tid + i * 256;
        int row = f / (KT / 8), u = f % (KT / 8);
        cp16(b_base + (row * LDB + u * 8) * 2,
             Bt + (size_t)(n0g + row) * KT + u * 8, 16u);
    }
    CP_COMMIT();

    float acc[4][4][4];
#pragma unroll
    for (int i = 0; i < 4; i++)
#pragma unroll
        for (int j = 0; j < 4; j++)
#pragma unroll
            for (int r = 0; r < 4; r++) acc[i][j][r] = 0.f;

    auto load_A = [&](int s, int kk) {
#pragma unroll
        for (int i = 0; i < 2; i++) {
            int f = tid + i * 256;
            int m = f >> 2, u = f & 3;
            int row = m0g + m;
            bool v = row < M;
            const __half* src = A;
            if (v) {
                int r = gidx ? gidx[row] : row;
                src = A + (size_t)r * KT + kk + u * 8;
            }
            cp16(a_base + s * ABUF + (m * LDA + u * 8) * 2, src, v ? 16u : 0u);
        }
        CP_COMMIT();
    };

    const int m_base = wm * 64, n_base = wn * 32;
    const int rql = lane >> 2, cql = lane & 3;

    uint32_t aoff[4], boff[2];
#pragma unroll
    for (int mt = 0; mt < 4; mt++)
        aoff[mt] = ((m_base + mt * 16 + (lane & 15)) * LDA + (lane >> 4) * 8) * 2;
#pragma unroll
    for (int p = 0; p < 2; p++) {
        int rowb = n_base + p * 16 + ((lane >> 4) & 1) * 8 + (lane & 7);
        boff[p] = (rowb * LDB + ((lane >> 3) & 1) * 8) * 2;
    }

    load_A(0, 0);
    load_A(1, BK);
    load_A(2, 2 * BK);

    for (int kt = 0; kt < ktiles; kt++) {
        const int rem = ktiles - 1 - kt;
        if (rem >= 2) CP_WAIT(2);
        else if (rem == 1) CP_WAIT(1);
        else CP_WAIT(0);
        __syncthreads();
        if (kt + 3 < ktiles) load_A((kt + 3) % STG, (kt + 3) * BK);

        const int s = kt % STG;
#pragma unroll
        for (int k0 = 0; k0 < BK; k0 += 16) {
            uint32_t af[4][4], bf[4][2];
            const uint32_t ab = a_base + s * ABUF + k0 * 2;
            const uint32_t bb = b_base + (kt * BK + k0) * 2;
#pragma unroll
            for (int mt = 0; mt < 4; mt++)
                ldsm_x4(af[mt][0], af[mt][1], af[mt][2], af[mt][3], ab + aoff[mt]);
#pragma unroll
            for (int p = 0; p < 2; p++)
                ldsm_x4(bf[2 * p][0], bf[2 * p][1], bf[2 * p + 1][0],
                        bf[2 * p + 1][1], bb + boff[p]);
#pragma unroll
            for (int mt = 0; mt < 4; mt++)
#pragma unroll
                for (int nt = 0; nt < 4; nt++)
                    mma_f16(acc[mt][nt], af[mt][0], af[mt][1], af[mt][2],
                            af[mt][3], bf[nt][0], bf[nt][1]);
        }
    }

#pragma unroll
    for (int mt = 0; mt < 4; mt++) {
#pragma unroll
        for (int half = 0; half < 2; half++) {
            int row = m0g + m_base + mt * 16 + rql + half * 8;
            if (row >= M) continue;
#pragma unroll
            for (int nt = 0; nt < 4; nt++) {
                int col = n0g + n_base + nt * 8 + cql * 2;
                float2 v;
                v.x = acc[mt][nt][half * 2 + 0];
                v.y = acc[mt][nt][half * 2 + 1];
                if (bias) { v.x += bias[col]; v.y += bias[col + 1]; }
                if (RELU) { v.x = fmaxf(v.x, 0.f); v.y = fmaxf(v.y, 0.f); }
                if (OUTH) {
                    *(__half2*)((__half*)Cv + (size_t)row * ldc + col) =
                        __floats2half2_rn(v.x, v.y);
                } else {
                    *(float2*)((float*)Cv + (size_t)row * ldc + col) = v;
                }
            }
        }
    }
}

// ---------------------------------------------------------------------------
// Merged layer-0 GEMM: all four combine GEMMs in one launch (176 CTAs).
// Per-block dispatch; runtime KT in {256,512}; relu everywhere; no bias.
// ---------------------------------------------------------------------------
__global__ __launch_bounds__(256, 1)
void k_gemm_l0(const __half* __restrict__ featH, const int* __restrict__ s1,
               const __half* __restrict__ pool1, const int* __restrict__ b12,
               const __half* __restrict__ pool0,
               const __half* __restrict__ Ws0t, const __half* __restrict__ Wn0t,
               __half* __restrict__ y1, float* __restrict__ y0)
{
    constexpr int BM = 128, BK = 32, STG = 4;
    constexpr int LDA = BK + 8;
    constexpr uint32_t ABUF = BM * LDA * 2;
    extern __shared__ __align__(16) __half sm[];

    int b = blockIdx.x;
    const __half* A; const int* gidx = nullptr; const __half* Bt;
    int M, KT; bool outh;
    __half* Ch = nullptr; float* Cf = nullptr;
    if (b < 80)       { A = featH; gidx = s1;  Bt = Ws0t; M = 2*N1;    KT = 256; outh = true;  Ch = y1; }
    else if (b < 160) { b -= 80;  A = pool1;             Bt = Wn0t; M = 2*N1;    KT = 512; outh = true;  Ch = y1 + 128; }
    else if (b < 168) { b -= 160; A = featH; gidx = b12; Bt = Ws0t; M = 2*BATCH; KT = 256; outh = false; Cf = y0; }
    else              { b -= 168; A = pool0;             Bt = Wn0t; M = 2*BATCH; KT = 512; outh = false; Cf = y0 + 128; }
    const int ldc = 256;
    const int m0g = b * BM;
    const int LDB = KT + 8;
    const int ktiles = KT / BK;
    const int kt8 = KT / 8;

    const int tid  = threadIdx.x;
    const int lane = tid & 31;
    const int warp = tid >> 5;
    const int wm = warp >> 2, wn = warp & 3;

    const uint32_t b_base = (uint32_t)__cvta_generic_to_shared(sm);
    const uint32_t a_base = b_base + 128 * (512 + 8) * 2;   // worst-case B extent

    // B slice: 128 rows x KT halves
    const int bch = 128 * kt8 / 256;
    for (int i = 0; i < bch; i++) {
        int f = tid + i * 256;
        int row = f / kt8, u = f % kt8;
        cp16(b_base + (row * LDB + u * 8) * 2,
             Bt + (size_t)row * KT + u * 8, 16u);
    }
    CP_COMMIT();

    float acc[4][4][4];
#pragma unroll
    for (int i = 0; i < 4; i++)
#pragma unroll
        for (int j = 0; j < 4; j++)
#pragma unroll
            for (int r = 0; r < 4; r++) acc[i][j][r] = 0.f;

    auto load_A = [&](int s, int kk) {
#pragma unroll
        for (int i = 0; i < 2; i++) {
            int f = tid + i * 256;
            int m = f >> 2, u = f & 3;
            int row = m0g + m;
            bool v = row < M;
            const __half* src = A;
            if (v) {
                int r = gidx ? gidx[row] : row;
                src = A + (size_t)r * KT + kk + u * 8;
            }
            cp16(a_base + s * ABUF + (m * LDA + u * 8) * 2, src, v ? 16u : 0u);
        }
        CP_COMMIT();
    };

    const int m_base = wm * 64, n_base = wn * 32;
    const int rql = lane >> 2, cql = lane & 3;

    uint32_t aoff[4], boff[2];
#pragma unroll
    for (int mt = 0; mt < 4; mt++)
        aoff[mt] = ((m_base + mt * 16 + (lane & 15)) * LDA + (lane >> 4) * 8) * 2;
#pragma unroll
    for (int p = 0; p < 2; p++) {
        int rowb = n_base + p * 16 + ((lane >> 4) & 1) * 8 + (lane & 7);
        boff[p] = (rowb * LDB + ((lane >> 3) & 1) * 8) * 2;
    }

    load_A(0, 0);
    load_A(1, BK);
    load_A(2, 2 * BK);

    for (int kt = 0; kt < ktiles; kt++) {
        const int rem = ktiles - 1 - kt;
        if (rem >= 2) CP_WAIT(2);
        else if (rem == 1) CP_WAIT(1);
        else CP_WAIT(0);
        __syncthreads();
        if (kt + 3 < ktiles) load_A((kt + 3) % STG, (kt + 3) * BK);

        const int s = kt % STG;
#pragma unroll
        for (int k0 = 0; k0 < BK; k0 += 16) {
            uint32_t af[4][4], bf[4][2];
            const uint32_t ab = a_base + s * ABUF + k0 * 2;
            const uint32_t bb = b_base + (kt * BK + k0) * 2;
#pragma unroll
            for (int mt = 0; mt < 4; mt++)
                ldsm_x4(af[mt][0], af[mt][1], af[mt][2], af[mt][3], ab + aoff[mt]);
#pragma unroll
            for (int p = 0; p < 2; p++)
                ldsm_x4(bf[2 * p][0], bf[2 * p][1], bf[2 * p + 1][0],
                        bf[2 * p + 1][1], bb + boff[p]);
#pragma unroll
            for (int mt = 0; mt < 4; mt++)
#pragma unroll
                for (int nt = 0; nt < 4; nt++)
                    mma_f16(acc[mt][nt], af[mt][0], af[mt][1], af[mt][2],
                            af[mt][3], bf[nt][0], bf[nt][1]);
        }
    }

#pragma unroll
    for (int mt = 0; mt < 4; mt++) {
#pragma unroll
        for (int half = 0; half < 2; half++) {
            int row = m0g + m_base + mt * 16 + rql + half * 8;
            if (row >= M) continue;
#pragma unroll
            for (int nt = 0; nt < 4; nt++) {
                int col = n_base + nt * 8 + cql * 2;
                float2 v;
                v.x = fmaxf(acc[mt][nt][half * 2 + 0], 0.f);
                v.y = fmaxf(acc[mt][nt][half * 2 + 1], 0.f);
                if (outh) {
                    *(__half2*)(Ch + (size_t)row * ldc + col) =
                        __floats2half2_rn(v.x, v.y);
                } else {
                    *(float2*)(Cf + (size_t)row * ldc + col) = v;
                }
            }
        }
    }
}

// ----------------- merged gather-max pools (fp16, one launch) ---------------
template<int NB>
__device__ __forceinline__ void pool_body(const __half* __restrict__ src,
                                          const int* __restrict__ idx,
                                          __half* __restrict__ dst,
                                          int* sidx)
{
    if (threadIdx.x < NB) sidx[threadIdx.x] = idx[threadIdx.x];
    __syncthreads();
    int c = threadIdx.x * 8;
    __half2 m0 = __float2half2_rn(0.f), m1 = m0, m2 = m0, m3 = m0;
#pragma unroll
    for (int j = 0; j < NB; j++) {
        uint4 v = *(const uint4*)(src + (size_t)sidx[j] * HIDW + c);
        const __half2* h = (const __half2*)&v;
        m0 = __hmax2(m0, h[0]);
        m1 = __hmax2(m1, h[1]);
        m2 = __hmax2(m2, h[2]);
        m3 = __hmax2(m3, h[3]);
    }
    __half2 r[4] = { m0, m1, m2, m3 };
    *(uint4*)(dst + c) = *(uint4*)r;
}

__global__ void k_pool_all(const __half* __restrict__ H)
{
    __shared__ int sidx[NS_A];
    int g = blockIdx.x;
    if (g < 2 * N1)
        pool_body<NS_A>(H, g_s2 + (size_t)g * NS_A, g_pool1 + (size_t)g * HIDW, sidx);
    else {
        g -= 2 * N1;
        pool_body<NS_B>(H, g_s1 + (size_t)g * NS_B, g_pool0 + (size_t)g * HIDW, sidx);
    }
}

// --------------------- segmented max (fp32, consecutive) --------------------
template<int NB>
__global__ void k_poolmax_f(const float* __restrict__ src, float* __restrict__ dst)
{
    int g = blockIdx.x;
    int c = threadIdx.x * 4;
    float4 m = make_float4(-1e30f, -1e30f, -1e30f, -1e30f);
#pragma unroll
    for (int j = 0; j < NB; j++) {
        const float4 v = *(const float4*)(src + (size_t)(g * NB + j) * HIDW + c);
        m.x = fmaxf(m.x, v.x);
        m.y = fmaxf(m.y, v.y);
        m.z = fmaxf(m.z, v.z);
        m.w = fmaxf(m.w, v.w);
    }
    *(float4*)(dst + (size_t)g * HIDW + c) = m;
}

// -------------------- layer-1 combine + L2 normalize ------------------------
__global__ void k_final(const float* __restrict__ y0, const float* __restrict__ p2,
                        const float* __restrict__ Ws1, const float* __restrict__ Wn1,
                        float* __restrict__ out)
{
    int n = blockIdx.x;
    __shared__ float ss[256];
    __shared__ float sp[512];
    __shared__ float red[256];
    int tid = threadIdx.x;
    ss[tid] = y0[(size_t)n * 256 + tid];
    sp[tid] = p2[(size_t)n * 512 + tid];
    sp[256 + tid] = p2[(size_t)n * 512 + 256 + tid];
    __syncthreads();

    float acc = 0.f;
    if (tid < 128) {
#pragma unroll 8
        for (int k = 0; k < 256; k++) acc += ss[k] * Ws1[k * 128 + tid];
    } else {
        int c = tid - 128;
#pragma unroll 8
        for (int k = 0; k < 512; k++) acc += sp[k] * Wn1[k * 128 + c];
    }
    red[tid] = acc * acc;
    __syncthreads();
    for (int s = 128; s > 0; s >>= 1) {
        if (tid < s) red[tid] += red[tid + s];
        __syncthreads();
    }
    float inv = 1.f / fmaxf(sqrtf(red[0]), 1e-12f);
    out[(size_t)n * 256 + tid] = acc * inv;
}

// ------------------------------- launcher -----------------------------------
#define SMEM_K256 ((128 * (256 + 8) + 4 * 128 * 40) * 2)   // 108544
#define SMEM_L0   ((128 * (512 + 8) + 4 * 128 * 40) * 2)   // 174080

extern "C" void kernel_launch(void* const* d_in, const int* in_sizes, int n_in,
                              void* d_out, int out_size)
{
    (void)in_sizes; (void)n_in; (void)out_size;
    const int*   b1   = (const int*)d_in[0];
    const int*   b2   = (const int*)d_in[1];
    const float* feat = (const float*)d_in[2];
    const int*   adj  = (const int*)d_in[3];
    const float* Wp0  = (const float*)d_in[4];
    const float* bp0  = (const float*)d_in[5];
    const float* Wn0  = (const float*)d_in[6];
    const float* Ws0  = (const float*)d_in[7];
    const float* Wp1  = (const float*)d_in[8];
    const float* bp1  = (const float*)d_in[9];
    const float* Wn1  = (const float*)d_in[10];
    const float* Ws1  = (const float*)d_in[11];
    float* out = (float*)d_out;

    int *s1, *s2, *b12;
    __half *featH, *H, *pool1, *pool0, *y1, *Wp0t, *Wn0t, *Ws0t, *Wp1t;
    float *y0, *T, *pool2;
    cudaGetSymbolAddress((void**)&s1,    g_s1);
    cudaGetSymbolAddress((void**)&s2,    g_s2);
    cudaGetSymbolAddress((void**)&b12,   g_b12);
    cudaGetSymbolAddress((void**)&featH, g_featH);
    cudaGetSymbolAddress((void**)&H,     g_H);
    cudaGetSymbolAddress((void**)&pool1, g_pool1);
    cudaGetSymbolAddress((void**)&pool0, g_pool0);
    cudaGetSymbolAddress((void**)&y1,    g_y1);
    cudaGetSymbolAddress((void**)&y0,    g_y0);
    cudaGetSymbolAddress((void**)&T,     g_T);
    cudaGetSymbolAddress((void**)&pool2, g_pool2);
    cudaGetSymbolAddress((void**)&Wp0t,  g_Wp0t);
    cudaGetSymbolAddress((void**)&Wn0t,  g_Wn0t);
    cudaGetSymbolAddress((void**)&Ws0t,  g_Ws0t);
    cudaGetSymbolAddress((void**)&Wp1t,  g_Wp1t);

    cudaFuncSetAttribute(k_gemm_bres<256, true,  true>,
                         cudaFuncAttributeMaxDynamicSharedMemorySize, SMEM_K256);
    cudaFuncSetAttribute(k_gemm_bres<256, false, true>,
                         cudaFuncAttributeMaxDynamicSharedMemorySize, SMEM_K256);
    cudaFuncSetAttribute(k_gemm_l0,
                         cudaFuncAttributeMaxDynamicSharedMemorySize, SMEM_L0);

    // 0,1: sampling   2: prep   3: H GEMM (ncu profiles launch index 3)
    k_sample1<<<(2 * N1 + 255) / 256, 256>>>(b1, b2, adj);
    k_sample2<<<(2 * N2 + 255) / 256, 256>>>(adj);
    k_prep<<<352 + 12500, 256>>>(Wp0, Wn0, Ws0, Wp1, feat);

    k_gemm_bres<256, true, true><<<dim3((NN + 127) / 128, HIDW / 128), 256, SMEM_K256>>>(
        featH, nullptr, NN, Wp0t, bp0, H, HIDW);

    // 4: both pools in one launch
    k_pool_all<<<2 * N1 + 2 * BATCH, 64>>>(H);

    // 5: all four layer-0 GEMMs in one launch (176 CTAs)
    k_gemm_l0<<<176, 256, SMEM_L0>>>(featH, s1, pool1, b12, pool0,
                                     Ws0t, Wn0t, y1, y0);

    // 6,7: layer-1 pool MLP + consecutive segmax
    k_gemm_bres<256, false, true><<<dim3(2 * N1 / 128, HIDW / 128), 256, SMEM_K256>>>(
        y1, nullptr, 2 * N1, Wp1t, bp1, T, HIDW);
    k_poolmax_f<NS_B><<<2 * BATCH, 128>>>(T, pool2);

    // 8: final combine + L2 normalize (exact fp32)
    k_final<<<2 * BATCH, 256>>>(y0, pool2, Ws1, Wn1, out);
}